// round 2
// baseline (speedup 1.0000x reference)
#include <cuda_runtime.h>
#include <math.h>

#define B_  32
#define TI_ 4096
#define D_  512
#define M_TOTAL (B_ * TI_)   /* 131072 */
#define NCHUNK 4             /* 512 / 128 d-chunks in scores kernel */
#define TSPLIT 16            /* t-splits in mix kernel */

// Scratch (static device globals: allocation-free, re-written fully every launch,
// no zero-init needed because every element is written before read).
__device__ float g_qk[B_ * D_];                    // q + bq + bk  (64 KB)
__device__ float g_scores_part[NCHUNK * M_TOTAL];  // partial scores per d-chunk (2 MB)
__device__ float g_attn[B_ * TI_];                 // softmax result (512 KB)
__device__ float g_mix_part[TSPLIT * B_ * D_];     // partial mix per t-split (1 MB)

// ---------------------------------------------------------------------------
// Kernel 1: g_qk[b][d] = dot(output[b,:], Wq[d,:]) + bq[d] + bk[d]
// One block per batch, warp-per-output-d (coalesced Wq row reads).
// ---------------------------------------------------------------------------
__global__ void k_query(const float* __restrict__ outp, const float* __restrict__ Wq,
                        const float* __restrict__ bq, const float* __restrict__ bk) {
    __shared__ float so[D_];
    int b = blockIdx.x;
    int tid = threadIdx.x;                 // 512 threads
    so[tid] = outp[b * D_ + tid];
    __syncthreads();
    int warp = tid >> 5, lane = tid & 31;
    for (int d = warp; d < D_; d += 16) {
        const float* w = Wq + (size_t)d * D_;
        float s = 0.f;
#pragma unroll 4
        for (int j = lane; j < D_; j += 32) s += so[j] * w[j];
#pragma unroll
        for (int o = 16; o > 0; o >>= 1) s += __shfl_down_sync(0xffffffffu, s, o);
        if (lane == 0) g_qk[b * D_ + d] = s + bq[d] + bk[d];
    }
}

// ---------------------------------------------------------------------------
// Kernel 2 (dominant): fused keys GEMM + tanh + Wv reduction.
// C[m][n] = sum_k context[m][k] * Wk[n][k]   (m = b*4096+t, n = d)
// partial_score[m] (for this 128-wide n-chunk) = sum_n Wv[n]*tanh(C + g_qk[b][n])
// Classic 128x128x8 SGEMM, 256 threads, 8x8 microtile (2x2 blocks of 4),
// register prefetch of next K-slice.
// ---------------------------------------------------------------------------
__global__ __launch_bounds__(256)
void k_scores(const float* __restrict__ ctx, const float* __restrict__ Wk,
              const float* __restrict__ Wv) {
    __shared__ float As[8][128];
    __shared__ float Bs[8][128];

    const int row0 = blockIdx.x * 128;     // global m tile (never crosses batch: 128 | 4096)
    const int n0   = blockIdx.y * 128;     // d chunk
    const int b    = row0 >> 12;           // / 4096
    const int tid  = threadIdx.x;
    const int tx   = tid & 15;
    const int ty   = tid >> 4;
    const int lrow = tid >> 1;             // 0..127
    const int lvec = (tid & 1) * 4;        // 0 or 4

    const float* Ap = ctx + (size_t)(row0 + lrow) * D_ + lvec;
    const float* Bp = Wk  + (size_t)(n0   + lrow) * D_ + lvec;

    float acc[2][2][4][4];
#pragma unroll
    for (int ri = 0; ri < 2; ++ri)
#pragma unroll
        for (int ci = 0; ci < 2; ++ci)
#pragma unroll
            for (int i = 0; i < 4; ++i)
#pragma unroll
                for (int j = 0; j < 4; ++j) acc[ri][ci][i][j] = 0.f;

    float4 a = *(const float4*)Ap;
    float4 w = *(const float4*)Bp;

    for (int kk = 0; kk < D_; kk += 8) {
        As[lvec + 0][lrow] = a.x; As[lvec + 1][lrow] = a.y;
        As[lvec + 2][lrow] = a.z; As[lvec + 3][lrow] = a.w;
        Bs[lvec + 0][lrow] = w.x; Bs[lvec + 1][lrow] = w.y;
        Bs[lvec + 2][lrow] = w.z; Bs[lvec + 3][lrow] = w.w;
        __syncthreads();

        if (kk + 8 < D_) {   // prefetch next K-slice into registers
            a = *(const float4*)(Ap + kk + 8);
            w = *(const float4*)(Bp + kk + 8);
        }

#pragma unroll
        for (int k = 0; k < 8; ++k) {
            float4 a0 = *(const float4*)&As[k][ty * 4];
            float4 a1 = *(const float4*)&As[k][64 + ty * 4];
            float4 b0 = *(const float4*)&Bs[k][tx * 4];
            float4 b1 = *(const float4*)&Bs[k][64 + tx * 4];
            float ar[2][4] = {{a0.x, a0.y, a0.z, a0.w}, {a1.x, a1.y, a1.z, a1.w}};
            float br[2][4] = {{b0.x, b0.y, b0.z, b0.w}, {b1.x, b1.y, b1.z, b1.w}};
#pragma unroll
            for (int ri = 0; ri < 2; ++ri)
#pragma unroll
                for (int i = 0; i < 4; ++i)
#pragma unroll
                    for (int ci = 0; ci < 2; ++ci)
#pragma unroll
                        for (int j = 0; j < 4; ++j)
                            acc[ri][ci][i][j] += ar[ri][i] * br[ci][j];
        }
        __syncthreads();
    }

    // Epilogue: tanh + Wv-weighted reduction over the 128 n's of this chunk.
    const float* qkb = g_qk + b * D_;
#pragma unroll
    for (int ri = 0; ri < 2; ++ri) {
#pragma unroll
        for (int i = 0; i < 4; ++i) {
            float s = 0.f;
#pragma unroll
            for (int ci = 0; ci < 2; ++ci) {
#pragma unroll
                for (int j = 0; j < 4; ++j) {
                    int n = n0 + ci * 64 + tx * 4 + j;
                    float v = tanhf(acc[ri][ci][i][j] + __ldg(&qkb[n]));
                    s += v * __ldg(&Wv[n]);
                }
            }
            // reduce across the 16 tx lanes (each half-warp shares one ty)
#pragma unroll
            for (int o = 1; o < 16; o <<= 1) s += __shfl_xor_sync(0xffffffffu, s, o);
            if (tx == 0) {
                int row = row0 + ri * 64 + ty * 4 + i;
                g_scores_part[blockIdx.y * M_TOTAL + row] = s;
            }
        }
    }
}

// ---------------------------------------------------------------------------
// Kernel 3: sum d-chunk partials, softmax over TI per batch. Writes g_attn
// (and d_out attn region if present). bv shift cancels in softmax -> ignored.
// ---------------------------------------------------------------------------
__global__ void k_softmax(float* __restrict__ attn_out) {
    __shared__ float s[TI_];
    __shared__ float red[256];
    int b = blockIdx.x, tid = threadIdx.x;   // 256 threads

    for (int t = tid; t < TI_; t += 256) {
        float v = 0.f;
#pragma unroll
        for (int p = 0; p < NCHUNK; ++p) v += g_scores_part[p * M_TOTAL + b * TI_ + t];
        s[t] = v;
    }
    __syncthreads();

    float m = -1e30f;
    for (int t = tid; t < TI_; t += 256) m = fmaxf(m, s[t]);
    red[tid] = m; __syncthreads();
    for (int o = 128; o > 0; o >>= 1) {
        if (tid < o) red[tid] = fmaxf(red[tid], red[tid + o]);
        __syncthreads();
    }
    m = red[0]; __syncthreads();

    float sum = 0.f;
    for (int t = tid; t < TI_; t += 256) { float e = expf(s[t] - m); s[t] = e; sum += e; }
    red[tid] = sum; __syncthreads();
    for (int o = 128; o > 0; o >>= 1) {
        if (tid < o) red[tid] += red[tid + o];
        __syncthreads();
    }
    float inv = 1.f / red[0];

    for (int t = tid; t < TI_; t += 256) {
        float av = s[t] * inv;
        g_attn[b * TI_ + t] = av;
        if (attn_out) attn_out[b * TI_ + t] = av;
    }
}

// ---------------------------------------------------------------------------
// Kernel 4: partial mix over 256-token t-splits (bandwidth-bound pass).
// mix_part[split][b][d] = sum_{t in split} attn[b][t] * context[b][t][d]
// ---------------------------------------------------------------------------
__global__ void k_mix(const float* __restrict__ ctx) {
    __shared__ float sa[256];
    int b = blockIdx.y, t0 = blockIdx.x * 256, tid = threadIdx.x;  // 256 threads
    sa[tid] = g_attn[b * TI_ + t0 + tid];
    __syncthreads();
    const float* cp = ctx + ((size_t)b * TI_ + t0) * D_;
    float a0 = 0.f, a1 = 0.f;
#pragma unroll 4
    for (int t = 0; t < 256; ++t) {
        float av = sa[t];
        a0 += av * cp[(size_t)t * D_ + tid];
        a1 += av * cp[(size_t)t * D_ + 256 + tid];
    }
    g_mix_part[(blockIdx.x * B_ + b) * D_ + tid]       = a0;
    g_mix_part[(blockIdx.x * B_ + b) * D_ + 256 + tid] = a1;
}

// ---------------------------------------------------------------------------
// Kernel 5: sum mix partials, concat with output, project through Wo, tanh.
// ---------------------------------------------------------------------------
__global__ void k_out(const float* __restrict__ outp, const float* __restrict__ Wo,
                      const float* __restrict__ bo, float* __restrict__ out_out,
                      float* __restrict__ mix_out) {
    __shared__ float comb[2 * D_];
    int b = blockIdx.x, tid = threadIdx.x;   // 512 threads
    float mv = 0.f;
#pragma unroll
    for (int sp = 0; sp < TSPLIT; ++sp) mv += g_mix_part[(sp * B_ + b) * D_ + tid];
    comb[tid] = mv;
    if (mix_out) mix_out[b * D_ + tid] = mv;
    comb[D_ + tid] = outp[b * D_ + tid];
    __syncthreads();

    int warp = tid >> 5, lane = tid & 31;
    for (int d = warp; d < D_; d += 16) {
        const float* w = Wo + (size_t)d * (2 * D_);
        float s = 0.f;
#pragma unroll 4
        for (int j = lane; j < 2 * D_; j += 32) s += comb[j] * w[j];
#pragma unroll
        for (int o = 16; o > 0; o >>= 1) s += __shfl_down_sync(0xffffffffu, s, o);
        if (lane == 0) out_out[b * D_ + d] = tanhf(s + bo[d]);
    }
}

// ---------------------------------------------------------------------------
extern "C" void kernel_launch(void* const* d_in, const int* in_sizes, int n_in,
                              void* d_out, int out_size) {
    (void)in_sizes; (void)n_in;
    const float* outp = (const float*)d_in[0];   // [32,1,512]
    const float* ctx  = (const float*)d_in[1];   // [32,4096,512]
    const float* Wq   = (const float*)d_in[2];   // [512,512]
    const float* bq   = (const float*)d_in[3];   // [512]
    const float* Wk   = (const float*)d_in[4];   // [512,512]
    const float* bk   = (const float*)d_in[5];   // [512]
    const float* Wv   = (const float*)d_in[6];   // [1,512]
    /* d_in[7] = bv: constant shift -> cancels in softmax, unused */
    const float* Wo   = (const float*)d_in[8];   // [512,1024]
    const float* bo   = (const float*)d_in[9];   // [512]

    float* o        = (float*)d_out;
    float* out_out  = o;                         // [32,1,512]
    float* attn_out = nullptr;
    float* mix_out  = nullptr;
    if (out_size >= B_ * D_ + B_ * TI_ + B_ * D_) {  // tuple (out, attn, mix) flattened
        attn_out = o + B_ * D_;
        mix_out  = o + B_ * D_ + B_ * TI_;
    }

    k_query<<<B_, 512>>>(outp, Wq, bq, bk);

    dim3 g2(M_TOTAL / 128, NCHUNK);
    k_scores<<<g2, 256>>>(ctx, Wk, Wv);

    k_softmax<<<B_, 256>>>(attn_out);

    dim3 g4(TI_ / 256, B_);
    k_mix<<<g4, 256>>>(ctx);

    k_out<<<B_, 512>>>(outp, Wo, bo, out_out, mix_out);
}

// round 5
// speedup vs baseline: 1.2875x; 1.2875x over previous
#include <cuda_runtime.h>
#include <cuda_bf16.h>
#include <math.h>
#include <stdint.h>

#define B_  32
#define TI_ 4096
#define D_  512
#define M_TOTAL (B_ * TI_)   /* 131072 */
#define NCHUNK 4             /* 512 / 128 n-chunks */
#define TSPLIT 16

// ---------------------------------------------------------------------------
// Device scratch (allocation-free; every element written before read each call)
// ---------------------------------------------------------------------------
__device__ float g_qk[B_ * D_];
__device__ float g_scores_part[NCHUNK * M_TOTAL];
__device__ float g_attn[M_TOTAL];
__device__ float g_mix_part[TSPLIT * B_ * D_];
__device__ __nv_bfloat16 g_WkH[D_ * D_];   // Wk hi bf16
__device__ __nv_bfloat16 g_WkL[D_ * D_];   // Wk lo bf16

// SW128 swizzle (Swizzle<3,4,3>) on tile-relative byte offsets
#define SWZ(off) ((off) ^ (((off) >> 3) & 0x70))

__device__ __forceinline__ uint32_t smem_u32(const void* p) {
    uint32_t a;
    asm("{ .reg .u64 t; cvta.to.shared.u64 t, %1; cvt.u32.u64 %0, t; }" : "=r"(a) : "l"(p));
    return a;
}
__device__ __forceinline__ void ldsm4(uint32_t* r, uint32_t addr) {
    asm volatile("ldmatrix.sync.aligned.m8n8.x4.shared.b16 {%0,%1,%2,%3}, [%4];"
                 : "=r"(r[0]), "=r"(r[1]), "=r"(r[2]), "=r"(r[3]) : "r"(addr));
}
__device__ __forceinline__ void mma_bf16(float* c, const uint32_t* a, uint32_t b0, uint32_t b1) {
    asm volatile("mma.sync.aligned.m16n8k16.row.col.f32.bf16.bf16.f32 "
                 "{%0,%1,%2,%3}, {%4,%5,%6,%7}, {%8,%9}, {%0,%1,%2,%3};"
                 : "+f"(c[0]), "+f"(c[1]), "+f"(c[2]), "+f"(c[3])
                 : "r"(a[0]), "r"(a[1]), "r"(a[2]), "r"(a[3]), "r"(b0), "r"(b1));
}
__device__ __forceinline__ float fast_tanhf(float x) {
    // tanh(x) = 1 - 2/(exp(2x)+1); exact at saturation (exp->inf or 0)
    return 1.0f - 2.0f / (__expf(2.0f * x) + 1.0f);
}

// ---------------------------------------------------------------------------
// SMEM layout for k_scores_mma (dynamic, 66 KB)
// Stage tile row = 128B: [hi 32 bf16 | lo 32 bf16], SW128-swizzled.
// ---------------------------------------------------------------------------
#define OFF_A0  0
#define OFF_B0  16384
#define OFF_A1  32768
#define OFF_B1  49152
#define OFF_QK  65536          /* 128 floats */
#define OFF_WV  66048          /* 128 floats */
#define OFF_RED 66560          /* 2 x 128 floats */
#define SMEM_SC 67584

// ---------------------------------------------------------------------------
// k_prep: Wk fp32 -> hi/lo bf16 global arrays (512 KB each)
// ---------------------------------------------------------------------------
__global__ void k_prep(const float* __restrict__ Wk) {
    int idx = blockIdx.x * 256 + threadIdx.x;       // 65536 threads, float4 each
    float4 v = ((const float4*)Wk)[idx];
    __nv_bfloat162 h01 = __floats2bfloat162_rn(v.x, v.y);
    __nv_bfloat162 h23 = __floats2bfloat162_rn(v.z, v.w);
    float2 f01 = __bfloat1622float2(h01);
    float2 f23 = __bfloat1622float2(h23);
    __nv_bfloat162 l01 = __floats2bfloat162_rn(v.x - f01.x, v.y - f01.y);
    __nv_bfloat162 l23 = __floats2bfloat162_rn(v.z - f23.x, v.w - f23.y);
    uint2 hw, lw;
    hw.x = reinterpret_cast<uint32_t&>(h01); hw.y = reinterpret_cast<uint32_t&>(h23);
    lw.x = reinterpret_cast<uint32_t&>(l01); lw.y = reinterpret_cast<uint32_t&>(l23);
    ((uint2*)g_WkH)[idx] = hw;
    ((uint2*)g_WkL)[idx] = lw;
}

// ---------------------------------------------------------------------------
// k_query: g_qk[b][d] = output[b] . Wq[d] + bq[d] + bk[d]
// ---------------------------------------------------------------------------
__global__ void k_query(const float* __restrict__ outp, const float* __restrict__ Wq,
                        const float* __restrict__ bq, const float* __restrict__ bk) {
    __shared__ float so[D_];
    int b = blockIdx.x, tid = threadIdx.x;          // 512 threads
    so[tid] = outp[b * D_ + tid];
    __syncthreads();
    int warp = tid >> 5, lane = tid & 31;
    for (int d = warp; d < D_; d += 16) {
        const float* w = Wq + (size_t)d * D_;
        float s = 0.f;
#pragma unroll 4
        for (int j = lane; j < D_; j += 32) s += so[j] * w[j];
#pragma unroll
        for (int o = 16; o > 0; o >>= 1) s += __shfl_down_sync(0xffffffffu, s, o);
        if (lane == 0) g_qk[b * D_ + d] = s + bq[d] + bk[d];
    }
}

// ---------------------------------------------------------------------------
// Load one 32-col K-chunk: ctx tile (fp32->hi/lo bf16) + Wk tile (bf16 copy)
// into swizzled smem stage. 2048 16B jobs over 256 threads.
// ---------------------------------------------------------------------------
__device__ __forceinline__ void load_chunk(const float* __restrict__ ctx,
                                           int m0, int n0, int kc,
                                           char* smA, char* smB, int tid) {
    const int col0 = kc * 32;
#pragma unroll
    for (int it = 0; it < 4; ++it) {               // A: 1024 jobs
        int j = tid + it * 256;
        int row = j >> 3, seg = j & 7;
        float4 v = *(const float4*)(ctx + (size_t)(m0 + row) * D_ + col0 + seg * 4);
        __nv_bfloat162 h01 = __floats2bfloat162_rn(v.x, v.y);
        __nv_bfloat162 h23 = __floats2bfloat162_rn(v.z, v.w);
        float2 f01 = __bfloat1622float2(h01);
        float2 f23 = __bfloat1622float2(h23);
        __nv_bfloat162 l01 = __floats2bfloat162_rn(v.x - f01.x, v.y - f01.y);
        __nv_bfloat162 l23 = __floats2bfloat162_rn(v.z - f23.x, v.w - f23.y);
        uint2 hw, lw;
        hw.x = reinterpret_cast<uint32_t&>(h01); hw.y = reinterpret_cast<uint32_t&>(h23);
        lw.x = reinterpret_cast<uint32_t&>(l01); lw.y = reinterpret_cast<uint32_t&>(l23);
        uint32_t base = (uint32_t)(row * 128 + seg * 8);
        *(uint2*)(smA + SWZ(base))      = hw;
        *(uint2*)(smA + SWZ(base + 64)) = lw;
    }
#pragma unroll
    for (int it = 0; it < 4; ++it) {               // B: 1024 jobs (16B copies)
        int j = tid + it * 256;
        int row = j >> 3, rest = j & 7;
        int h = rest >> 2, seg = rest & 3;
        const __nv_bfloat16* src = (h ? g_WkL : g_WkH) + (size_t)(n0 + row) * D_ + col0 + seg * 8;
        uint4 v = *(const uint4*)src;
        *(uint4*)(smB + SWZ((uint32_t)(row * 128 + h * 64 + seg * 16))) = v;
    }
}

// ---------------------------------------------------------------------------
// k_scores_mma (dominant): bf16x3 split GEMM via mma.sync + tanh/Wv epilogue.
// Grid (NCHUNK, 1024), 256 threads (8 warps; warp = 32m x 64n).
// ---------------------------------------------------------------------------
__global__ void __launch_bounds__(256, 1)
k_scores_mma(const float* __restrict__ ctx, const float* __restrict__ Wv) {
    extern __shared__ char smem[];
    const int tid  = threadIdx.x;
    const int lane = tid & 31, wid = tid >> 5;
    const int wm = wid >> 1, wn = wid & 1;
    const int n0 = blockIdx.x * 128;
    const int m0 = blockIdx.y * 128;
    const int b  = m0 >> 12;

    float* sQk  = (float*)(smem + OFF_QK);
    float* sWv  = (float*)(smem + OFF_WV);
    float* sred = (float*)(smem + OFF_RED);
    if (tid < 128) { sQk[tid] = g_qk[b * D_ + n0 + tid]; sWv[tid] = Wv[n0 + tid]; }

    // per-lane ldmatrix address constants
    const int q = lane >> 3, r = lane & 7;
    const uint32_t rowA  = wm * 32 + ((q & 1) << 3) + r;
    const uint32_t segA  = (q >> 1) << 4;
    const uint32_t xorA  = (rowA & 7) << 4;
    const uint32_t baseA = rowA << 7;
    const uint32_t rowB  = wn * 64 + ((q >> 1) << 3) + r;
    const uint32_t segB  = (q & 1) << 4;
    const uint32_t xorB  = (rowB & 7) << 4;
    const uint32_t baseB = rowB << 7;

    const uint32_t sb = smem_u32(smem);
    const uint32_t sA[2] = { sb + OFF_A0, sb + OFF_A1 };
    const uint32_t sB[2] = { sb + OFF_B0, sb + OFF_B1 };

    float acc[2][8][4];
#pragma unroll
    for (int mi = 0; mi < 2; ++mi)
#pragma unroll
        for (int nt = 0; nt < 8; ++nt)
#pragma unroll
            for (int c = 0; c < 4; ++c) acc[mi][nt][c] = 0.f;

    load_chunk(ctx, m0, n0, 0, smem + OFF_A0, smem + OFF_B0, tid);
    __syncthreads();

    for (int kc = 0; kc < 16; ++kc) {
        const int s = kc & 1;
        if (kc + 1 < 16)
            load_chunk(ctx, m0, n0, kc + 1,
                       smem + (s ? OFF_A0 : OFF_A1), smem + (s ? OFF_B0 : OFF_B1), tid);

#pragma unroll
        for (int ks = 0; ks < 2; ++ks) {
            uint32_t a[2][2][4];   // [h][mi][4]
            uint32_t bb[2][4][4];  // [h][np][4]
#pragma unroll
            for (int h = 0; h < 2; ++h)
#pragma unroll
                for (int mi = 0; mi < 2; ++mi)
                    ldsm4(a[h][mi], sA[s] + baseA + mi * 2048 +
                          (((uint32_t)(h * 64 + ks * 32) + segA) ^ xorA));
#pragma unroll
            for (int h = 0; h < 2; ++h)
#pragma unroll
                for (int np = 0; np < 4; ++np)
                    ldsm4(bb[h][np], sB[s] + baseB + np * 2048 +
                          (((uint32_t)(h * 64 + ks * 32) + segB) ^ xorB));
#pragma unroll
            for (int mi = 0; mi < 2; ++mi)
#pragma unroll
                for (int np = 0; np < 4; ++np)
#pragma unroll
                    for (int half = 0; half < 2; ++half) {
                        float* c = acc[mi][np * 2 + half];
                        uint32_t bh0 = bb[0][np][half * 2], bh1 = bb[0][np][half * 2 + 1];
                        uint32_t bl0 = bb[1][np][half * 2], bl1 = bb[1][np][half * 2 + 1];
                        mma_bf16(c, a[0][mi], bh0, bh1);   // HH
                        mma_bf16(c, a[0][mi], bl0, bl1);   // HL
                        mma_bf16(c, a[1][mi], bh0, bh1);   // LH
                    }
        }
        __syncthreads();
    }

    // Epilogue: score_part[row] = sum_n Wv[n] * tanh(acc + qk[n]) over 128 cols
#pragma unroll
    for (int mi = 0; mi < 2; ++mi) {
#pragma unroll
        for (int part = 0; part < 2; ++part) {
            float s = 0.f;
#pragma unroll
            for (int nt = 0; nt < 8; ++nt) {
                int col = wn * 64 + nt * 8 + 2 * (lane & 3);
                s += sWv[col]     * fast_tanhf(acc[mi][nt][part * 2]     + sQk[col]);
                s += sWv[col + 1] * fast_tanhf(acc[mi][nt][part * 2 + 1] + sQk[col + 1]);
            }
            s += __shfl_xor_sync(0xffffffffu, s, 1);
            s += __shfl_xor_sync(0xffffffffu, s, 2);
            if ((lane & 3) == 0)
                sred[wn * 128 + wm * 32 + mi * 16 + part * 8 + (lane >> 2)] = s;
        }
    }
    __syncthreads();
    if (tid < 128)
        g_scores_part[blockIdx.x * M_TOTAL + m0 + tid] = sred[tid] + sred[128 + tid];
}

// ---------------------------------------------------------------------------
// k_softmax: sum n-chunk partials, softmax over TI per batch
// ---------------------------------------------------------------------------
__global__ void k_softmax(float* __restrict__ attn_out) {
    __shared__ float s[TI_];
    __shared__ float red[256];
    int b = blockIdx.x, tid = threadIdx.x;   // 256 threads

    for (int t = tid; t < TI_; t += 256) {
        float v = 0.f;
#pragma unroll
        for (int p = 0; p < NCHUNK; ++p) v += g_scores_part[p * M_TOTAL + b * TI_ + t];
        s[t] = v;
    }
    __syncthreads();

    float m = -1e30f;
    for (int t = tid; t < TI_; t += 256) m = fmaxf(m, s[t]);
    red[tid] = m; __syncthreads();
    for (int o = 128; o > 0; o >>= 1) {
        if (tid < o) red[tid] = fmaxf(red[tid], red[tid + o]);
        __syncthreads();
    }
    m = red[0]; __syncthreads();

    float sum = 0.f;
    for (int t = tid; t < TI_; t += 256) { float e = expf(s[t] - m); s[t] = e; sum += e; }
    red[tid] = sum; __syncthreads();
    for (int o = 128; o > 0; o >>= 1) {
        if (tid < o) red[tid] += red[tid + o];
        __syncthreads();
    }
    float inv = 1.f / red[0];

    for (int t = tid; t < TI_; t += 256) {
        float av = s[t] * inv;
        g_attn[b * TI_ + t] = av;
        if (attn_out) attn_out[b * TI_ + t] = av;
    }
}

// ---------------------------------------------------------------------------
// k_mix: mix partials over 256-token splits, float4 loads
// ---------------------------------------------------------------------------
__global__ void k_mix(const float* __restrict__ ctx) {
    __shared__ float sa[256];
    int b = blockIdx.y, t0 = blockIdx.x * 256, tid = threadIdx.x;  // 128 threads
    sa[tid]       = g_attn[b * TI_ + t0 + tid];
    sa[tid + 128] = g_attn[b * TI_ + t0 + tid + 128];
    __syncthreads();
    const float4* cp = (const float4*)(ctx + ((size_t)b * TI_ + t0) * D_);
    float4 acc = make_float4(0.f, 0.f, 0.f, 0.f);
#pragma unroll 8
    for (int t = 0; t < 256; ++t) {
        float av = sa[t];
        float4 v = cp[(size_t)t * 128 + tid];
        acc.x += av * v.x; acc.y += av * v.y; acc.z += av * v.z; acc.w += av * v.w;
    }
    ((float4*)&g_mix_part[(blockIdx.x * B_ + b) * D_])[tid] = acc;
}

// ---------------------------------------------------------------------------
// k_out: reduce mix partials, concat with output, Wo projection + tanh
// ---------------------------------------------------------------------------
__global__ void k_out(const float* __restrict__ outp, const float* __restrict__ Wo,
                      const float* __restrict__ bo, float* __restrict__ out_out,
                      float* __restrict__ mix_out) {
    __shared__ float comb[2 * D_];
    int b = blockIdx.x, tid = threadIdx.x;   // 512 threads
    float mv = 0.f;
#pragma unroll
    for (int sp = 0; sp < TSPLIT; ++sp) mv += g_mix_part[(sp * B_ + b) * D_ + tid];
    comb[tid] = mv;
    if (mix_out) mix_out[b * D_ + tid] = mv;
    comb[D_ + tid] = outp[b * D_ + tid];
    __syncthreads();

    int warp = tid >> 5, lane = tid & 31;
    for (int d = warp; d < D_; d += 16) {
        const float* w = Wo + (size_t)d * (2 * D_);
        float s = 0.f;
#pragma unroll 4
        for (int j = lane; j < 2 * D_; j += 32) s += comb[j] * w[j];
#pragma unroll
        for (int o = 16; o > 0; o >>= 1) s += __shfl_down_sync(0xffffffffu, s, o);
        if (lane == 0) out_out[b * D_ + d] = tanhf(s + bo[d]);
    }
}

// ---------------------------------------------------------------------------
extern "C" void kernel_launch(void* const* d_in, const int* in_sizes, int n_in,
                              void* d_out, int out_size) {
    (void)in_sizes; (void)n_in;
    const float* outp = (const float*)d_in[0];
    const float* ctx  = (const float*)d_in[1];
    const float* Wq   = (const float*)d_in[2];
    const float* bq   = (const float*)d_in[3];
    const float* Wk   = (const float*)d_in[4];
    const float* bk   = (const float*)d_in[5];
    const float* Wv   = (const float*)d_in[6];
    /* d_in[7] = bv: cancels in softmax */
    const float* Wo   = (const float*)d_in[8];
    const float* bo   = (const float*)d_in[9];

    float* o        = (float*)d_out;
    float* out_out  = o;
    float* attn_out = nullptr;
    float* mix_out  = nullptr;
    if (out_size >= B_ * D_ + B_ * TI_ + B_ * D_) {
        attn_out = o + B_ * D_;
        mix_out  = o + B_ * D_ + B_ * TI_;
    }

    cudaFuncSetAttribute(k_scores_mma, cudaFuncAttributeMaxDynamicSharedMemorySize, SMEM_SC);

    k_prep<<<256, 256>>>(Wk);
    k_query<<<B_, 512>>>(outp, Wq, bq, bk);
    k_scores_mma<<<dim3(NCHUNK, M_TOTAL / 128), 256, SMEM_SC>>>(ctx, Wv);
    k_softmax<<<B_, 256>>>(attn_out);
    k_mix<<<dim3(TSPLIT, B_), 128>>>(ctx);
    k_out<<<B_, 512>>>(outp, Wo, bo, out_out, mix_out);
}

// round 6
// speedup vs baseline: 1.6217x; 1.2596x over previous
#include <cuda_runtime.h>
#include <cuda_bf16.h>
#include <math.h>
#include <stdint.h>

#define B_  32
#define TI_ 4096
#define D_  512
#define M_TOTAL (B_ * TI_)   /* 131072 */
#define NCHUNK 4             /* 512 / 128 n-chunks */
#define TSPLIT 16

// ---------------------------------------------------------------------------
// Device scratch (allocation-free; every element written before read each call)
// ---------------------------------------------------------------------------
__device__ float g_qk[B_ * D_];
__device__ float g_scores_part[NCHUNK * M_TOTAL];
__device__ float g_attn[M_TOTAL];
__device__ float g_mix_part[TSPLIT * B_ * D_];
__device__ __nv_bfloat16 g_WkH[D_ * D_];   // Wk hi bf16
__device__ __nv_bfloat16 g_WkL[D_ * D_];   // Wk lo bf16

// SW128 swizzle (Swizzle<3,4,3>) on tile-relative byte offsets
#define SWZ(off) ((off) ^ (((off) >> 3) & 0x70))

__device__ __forceinline__ uint32_t smem_u32(const void* p) {
    uint32_t a;
    asm("{ .reg .u64 t; cvta.to.shared.u64 t, %1; cvt.u32.u64 %0, t; }" : "=r"(a) : "l"(p));
    return a;
}
__device__ __forceinline__ void ldsm4(uint32_t* r, uint32_t addr) {
    asm volatile("ldmatrix.sync.aligned.m8n8.x4.shared.b16 {%0,%1,%2,%3}, [%4];"
                 : "=r"(r[0]), "=r"(r[1]), "=r"(r[2]), "=r"(r[3]) : "r"(addr));
}
__device__ __forceinline__ void mma_bf16(float* c, const uint32_t* a, uint32_t b0, uint32_t b1) {
    asm volatile("mma.sync.aligned.m16n8k16.row.col.f32.bf16.bf16.f32 "
                 "{%0,%1,%2,%3}, {%4,%5,%6,%7}, {%8,%9}, {%0,%1,%2,%3};"
                 : "+f"(c[0]), "+f"(c[1]), "+f"(c[2]), "+f"(c[3])
                 : "r"(a[0]), "r"(a[1]), "r"(a[2]), "r"(a[3]), "r"(b0), "r"(b1));
}
__device__ __forceinline__ void cp_async16(uint32_t dst, const void* src) {
    asm volatile("cp.async.cg.shared.global [%0], [%1], 16;" :: "r"(dst), "l"(src));
}
#define CP_COMMIT() asm volatile("cp.async.commit_group;" ::: "memory")
#define CP_WAIT0()  asm volatile("cp.async.wait_group 0;" ::: "memory")

__device__ __forceinline__ float fast_tanhf(float x) {
    // tanh(x) = 1 - 2/(exp(2x)+1); exact at saturation (exp->inf or 0)
    return 1.0f - 2.0f / (__expf(2.0f * x) + 1.0f);
}

// ---------------------------------------------------------------------------
// SMEM layout for k_scores_mma (dynamic, 66 KB)
// Stage tile row = 128B: [hi 32 bf16 | lo 32 bf16], SW128-swizzled.
// ---------------------------------------------------------------------------
#define OFF_A0  0
#define OFF_B0  16384
#define OFF_A1  32768
#define OFF_B1  49152
#define OFF_QK  65536          /* 128 floats */
#define OFF_WV  66048          /* 128 floats */
#define OFF_RED 66560          /* 2 x 128 floats */
#define SMEM_SC 67584

// ---------------------------------------------------------------------------
// k_prep: Wk fp32 -> hi/lo bf16 global arrays (512 KB each)
// ---------------------------------------------------------------------------
__global__ void k_prep(const float* __restrict__ Wk) {
    int idx = blockIdx.x * 256 + threadIdx.x;       // 65536 threads, float4 each
    float4 v = ((const float4*)Wk)[idx];
    __nv_bfloat162 h01 = __floats2bfloat162_rn(v.x, v.y);
    __nv_bfloat162 h23 = __floats2bfloat162_rn(v.z, v.w);
    float2 f01 = __bfloat1622float2(h01);
    float2 f23 = __bfloat1622float2(h23);
    __nv_bfloat162 l01 = __floats2bfloat162_rn(v.x - f01.x, v.y - f01.y);
    __nv_bfloat162 l23 = __floats2bfloat162_rn(v.z - f23.x, v.w - f23.y);
    uint2 hw, lw;
    hw.x = reinterpret_cast<uint32_t&>(h01); hw.y = reinterpret_cast<uint32_t&>(h23);
    lw.x = reinterpret_cast<uint32_t&>(l01); lw.y = reinterpret_cast<uint32_t&>(l23);
    ((uint2*)g_WkH)[idx] = hw;
    ((uint2*)g_WkL)[idx] = lw;
}

// ---------------------------------------------------------------------------
// k_query: g_qk[b][d] = output[b] . Wq[d] + bq[d] + bk[d]
// ---------------------------------------------------------------------------
__global__ void k_query(const float* __restrict__ outp, const float* __restrict__ Wq,
                        const float* __restrict__ bq, const float* __restrict__ bk) {
    __shared__ float so[D_];
    int b = blockIdx.x, tid = threadIdx.x;          // 512 threads
    so[tid] = outp[b * D_ + tid];
    __syncthreads();
    int warp = tid >> 5, lane = tid & 31;
    for (int d = warp; d < D_; d += 16) {
        const float* w = Wq + (size_t)d * D_;
        float s = 0.f;
#pragma unroll 4
        for (int j = lane; j < D_; j += 32) s += so[j] * w[j];
#pragma unroll
        for (int o = 16; o > 0; o >>= 1) s += __shfl_down_sync(0xffffffffu, s, o);
        if (lane == 0) g_qk[b * D_ + d] = s + bq[d] + bk[d];
    }
}

// ---------------------------------------------------------------------------
// Pipelined stage-fill pieces for k_scores_mma.
// A (ctx, needs fp32->hi/lo conversion): LDG into registers early, convert+STS late.
// B (Wk hi/lo, already bf16): cp.async direct global->smem.
// ---------------------------------------------------------------------------
__device__ __forceinline__ void ldA(const float* __restrict__ ctx,
                                    int m0, int kc, int tid, float4* Av) {
    const int col0 = kc * 32;
#pragma unroll
    for (int it = 0; it < 4; ++it) {
        int j = tid + it * 256;
        int row = j >> 3, seg = j & 7;
        Av[it] = *(const float4*)(ctx + (size_t)(m0 + row) * D_ + col0 + seg * 4);
    }
}

__device__ __forceinline__ void cvtStoreA(char* smA, int tid, const float4* Av) {
#pragma unroll
    for (int it = 0; it < 4; ++it) {
        int j = tid + it * 256;
        int row = j >> 3, seg = j & 7;
        float4 v = Av[it];
        __nv_bfloat162 h01 = __floats2bfloat162_rn(v.x, v.y);
        __nv_bfloat162 h23 = __floats2bfloat162_rn(v.z, v.w);
        float2 f01 = __bfloat1622float2(h01);
        float2 f23 = __bfloat1622float2(h23);
        __nv_bfloat162 l01 = __floats2bfloat162_rn(v.x - f01.x, v.y - f01.y);
        __nv_bfloat162 l23 = __floats2bfloat162_rn(v.z - f23.x, v.w - f23.y);
        uint2 hw, lw;
        hw.x = reinterpret_cast<uint32_t&>(h01); hw.y = reinterpret_cast<uint32_t&>(h23);
        lw.x = reinterpret_cast<uint32_t&>(l01); lw.y = reinterpret_cast<uint32_t&>(l23);
        uint32_t base = (uint32_t)(row * 128 + seg * 8);
        *(uint2*)(smA + SWZ(base))      = hw;
        *(uint2*)(smA + SWZ(base + 64)) = lw;
    }
}

__device__ __forceinline__ void cpB(int n0, int kc, uint32_t smB, int tid) {
    const int col0 = kc * 32;
#pragma unroll
    for (int it = 0; it < 4; ++it) {
        int j = tid + it * 256;
        int row = j >> 3, rest = j & 7;
        int h = rest >> 2, seg = rest & 3;
        const __nv_bfloat16* src = (h ? g_WkL : g_WkH) + (size_t)(n0 + row) * D_ + col0 + seg * 8;
        cp_async16(smB + SWZ((uint32_t)(row * 128 + h * 64 + seg * 16)), src);
    }
}

// ---------------------------------------------------------------------------
// k_scores_mma (dominant): bf16x3 split GEMM via mma.sync + tanh/Wv epilogue.
// Grid (NCHUNK, 1024), 256 threads (8 warps; warp = 32m x 64n).
// Explicit pipeline: loads for chunk kc+1 issued BEFORE the MMAs of chunk kc.
// ---------------------------------------------------------------------------
__global__ void __launch_bounds__(256, 1)
k_scores_mma(const float* __restrict__ ctx, const float* __restrict__ Wv) {
    extern __shared__ char smem[];
    const int tid  = threadIdx.x;
    const int lane = tid & 31, wid = tid >> 5;
    const int wm = wid >> 1, wn = wid & 1;
    const int n0 = blockIdx.x * 128;
    const int m0 = blockIdx.y * 128;
    const int b  = m0 >> 12;

    float* sQk  = (float*)(smem + OFF_QK);
    float* sWv  = (float*)(smem + OFF_WV);
    float* sred = (float*)(smem + OFF_RED);
    if (tid < 128) { sQk[tid] = g_qk[b * D_ + n0 + tid]; sWv[tid] = Wv[n0 + tid]; }

    // per-lane ldmatrix address constants
    const int q = lane >> 3, r = lane & 7;
    const uint32_t rowA  = wm * 32 + ((q & 1) << 3) + r;
    const uint32_t segA  = (q >> 1) << 4;
    const uint32_t xorA  = (rowA & 7) << 4;
    const uint32_t baseA = rowA << 7;
    const uint32_t rowB  = wn * 64 + ((q >> 1) << 3) + r;
    const uint32_t segB  = (q & 1) << 4;
    const uint32_t xorB  = (rowB & 7) << 4;
    const uint32_t baseB = rowB << 7;

    const uint32_t sb = smem_u32(smem);
    const uint32_t sA[2] = { sb + OFF_A0, sb + OFF_A1 };
    const uint32_t sBa[2] = { sb + OFF_B0, sb + OFF_B1 };
    char* const smA[2] = { smem + OFF_A0, smem + OFF_A1 };

    float acc[2][8][4];
#pragma unroll
    for (int mi = 0; mi < 2; ++mi)
#pragma unroll
        for (int nt = 0; nt < 8; ++nt)
#pragma unroll
            for (int c = 0; c < 4; ++c) acc[mi][nt][c] = 0.f;

    float4 Av[4];
    // Prologue: fill stage 0
    cpB(n0, 0, sBa[0], tid);
    CP_COMMIT();
    ldA(ctx, m0, 0, tid, Av);
    cvtStoreA(smA[0], tid, Av);
    CP_WAIT0();
    __syncthreads();

    for (int kc = 0; kc < 16; ++kc) {
        const int s = kc & 1;
        if (kc + 1 < 16) {
            cpB(n0, kc + 1, sBa[1 - s], tid);   // async fill of other B stage
            CP_COMMIT();
            ldA(ctx, m0, kc + 1, tid, Av);       // LDG in flight during MMAs
        }

#pragma unroll
        for (int ks = 0; ks < 2; ++ks) {
            uint32_t a[2][2][4];   // [h][mi][4]
            uint32_t bb[2][4][4];  // [h][np][4]
#pragma unroll
            for (int h = 0; h < 2; ++h)
#pragma unroll
                for (int mi = 0; mi < 2; ++mi)
                    ldsm4(a[h][mi], sA[s] + baseA + mi * 2048 +
                          (((uint32_t)(h * 64 + ks * 32) + segA) ^ xorA));
#pragma unroll
            for (int h = 0; h < 2; ++h)
#pragma unroll
                for (int np = 0; np < 4; ++np)
                    ldsm4(bb[h][np], sBa[s] + baseB + np * 2048 +
                          (((uint32_t)(h * 64 + ks * 32) + segB) ^ xorB));
#pragma unroll
            for (int mi = 0; mi < 2; ++mi)
#pragma unroll
                for (int np = 0; np < 4; ++np)
#pragma unroll
                    for (int half = 0; half < 2; ++half) {
                        float* c = acc[mi][np * 2 + half];
                        uint32_t bh0 = bb[0][np][half * 2], bh1 = bb[0][np][half * 2 + 1];
                        uint32_t bl0 = bb[1][np][half * 2], bl1 = bb[1][np][half * 2 + 1];
                        mma_bf16(c, a[0][mi], bh0, bh1);   // HH
                        mma_bf16(c, a[0][mi], bl0, bl1);   // HL
                        mma_bf16(c, a[1][mi], bh0, bh1);   // LH
                    }
        }

        if (kc + 1 < 16) cvtStoreA(smA[1 - s], tid, Av);   // convert+STS after MMAs
        CP_WAIT0();
        __syncthreads();
    }

    // Epilogue: score_part[row] = sum_n Wv[n] * tanh(acc + qk[n]) over 128 cols
#pragma unroll
    for (int mi = 0; mi < 2; ++mi) {
#pragma unroll
        for (int part = 0; part < 2; ++part) {
            float s = 0.f;
#pragma unroll
            for (int nt = 0; nt < 8; ++nt) {
                int col = wn * 64 + nt * 8 + 2 * (lane & 3);
                s += sWv[col]     * fast_tanhf(acc[mi][nt][part * 2]     + sQk[col]);
                s += sWv[col + 1] * fast_tanhf(acc[mi][nt][part * 2 + 1] + sQk[col + 1]);
            }
            s += __shfl_xor_sync(0xffffffffu, s, 1);
            s += __shfl_xor_sync(0xffffffffu, s, 2);
            if ((lane & 3) == 0)
                sred[wn * 128 + wm * 32 + mi * 16 + part * 8 + (lane >> 2)] = s;
        }
    }
    __syncthreads();
    if (tid < 128)
        g_scores_part[blockIdx.x * M_TOTAL + m0 + tid] = sred[tid] + sred[128 + tid];
}

// ---------------------------------------------------------------------------
// k_softmax: sum n-chunk partials, softmax over TI per batch (512 threads)
// ---------------------------------------------------------------------------
__global__ void k_softmax(float* __restrict__ attn_out) {
    __shared__ float s[TI_];
    __shared__ float red[512];
    int b = blockIdx.x, tid = threadIdx.x;   // 512 threads

    for (int t = tid; t < TI_; t += 512) {
        float v = 0.f;
#pragma unroll
        for (int p = 0; p < NCHUNK; ++p) v += g_scores_part[p * M_TOTAL + b * TI_ + t];
        s[t] = v;
    }
    __syncthreads();

    float m = -1e30f;
    for (int t = tid; t < TI_; t += 512) m = fmaxf(m, s[t]);
    red[tid] = m; __syncthreads();
    for (int o = 256; o > 0; o >>= 1) {
        if (tid < o) red[tid] = fmaxf(red[tid], red[tid + o]);
        __syncthreads();
    }
    m = red[0]; __syncthreads();

    float sum = 0.f;
    for (int t = tid; t < TI_; t += 512) { float e = expf(s[t] - m); s[t] = e; sum += e; }
    red[tid] = sum; __syncthreads();
    for (int o = 256; o > 0; o >>= 1) {
        if (tid < o) red[tid] += red[tid + o];
        __syncthreads();
    }
    float inv = 1.f / red[0];

    for (int t = tid; t < TI_; t += 512) {
        float av = s[t] * inv;
        g_attn[b * TI_ + t] = av;
        if (attn_out) attn_out[b * TI_ + t] = av;
    }
}

// ---------------------------------------------------------------------------
// k_mix: mix partials over 256-token splits, float4 loads
// ---------------------------------------------------------------------------
__global__ void k_mix(const float* __restrict__ ctx) {
    __shared__ float sa[256];
    int b = blockIdx.y, t0 = blockIdx.x * 256, tid = threadIdx.x;  // 128 threads
    sa[tid]       = g_attn[b * TI_ + t0 + tid];
    sa[tid + 128] = g_attn[b * TI_ + t0 + tid + 128];
    __syncthreads();
    const float4* cp = (const float4*)(ctx + ((size_t)b * TI_ + t0) * D_);
    float4 acc = make_float4(0.f, 0.f, 0.f, 0.f);
#pragma unroll 8
    for (int t = 0; t < 256; ++t) {
        float av = sa[t];
        float4 v = cp[(size_t)t * 128 + tid];
        acc.x += av * v.x; acc.y += av * v.y; acc.z += av * v.z; acc.w += av * v.w;
    }
    ((float4*)&g_mix_part[(blockIdx.x * B_ + b) * D_])[tid] = acc;
}

// ---------------------------------------------------------------------------
// k_out: reduce mix partials, concat with output, Wo projection + tanh
// ---------------------------------------------------------------------------
__global__ void k_out(const float* __restrict__ outp, const float* __restrict__ Wo,
                      const float* __restrict__ bo, float* __restrict__ out_out,
                      float* __restrict__ mix_out) {
    __shared__ float comb[2 * D_];
    int b = blockIdx.x, tid = threadIdx.x;   // 512 threads
    float mv = 0.f;
#pragma unroll
    for (int sp = 0; sp < TSPLIT; ++sp) mv += g_mix_part[(sp * B_ + b) * D_ + tid];
    comb[tid] = mv;
    if (mix_out) mix_out[b * D_ + tid] = mv;
    comb[D_ + tid] = outp[b * D_ + tid];
    __syncthreads();

    int warp = tid >> 5, lane = tid & 31;
    for (int d = warp; d < D_; d += 16) {
        const float* w = Wo + (size_t)d * (2 * D_);
        float s = 0.f;
#pragma unroll 4
        for (int j = lane; j < 2 * D_; j += 32) s += comb[j] * w[j];
#pragma unroll
        for (int o = 16; o > 0; o >>= 1) s += __shfl_down_sync(0xffffffffu, s, o);
        if (lane == 0) out_out[b * D_ + d] = tanhf(s + bo[d]);
    }
}

// ---------------------------------------------------------------------------
extern "C" void kernel_launch(void* const* d_in, const int* in_sizes, int n_in,
                              void* d_out, int out_size) {
    (void)in_sizes; (void)n_in;
    const float* outp = (const float*)d_in[0];
    const float* ctx  = (const float*)d_in[1];
    const float* Wq   = (const float*)d_in[2];
    const float* bq   = (const float*)d_in[3];
    const float* Wk   = (const float*)d_in[4];
    const float* bk   = (const float*)d_in[5];
    const float* Wv   = (const float*)d_in[6];
    /* d_in[7] = bv: cancels in softmax */
    const float* Wo   = (const float*)d_in[8];
    const float* bo   = (const float*)d_in[9];

    float* o        = (float*)d_out;
    float* out_out  = o;
    float* attn_out = nullptr;
    float* mix_out  = nullptr;
    if (out_size >= B_ * D_ + B_ * TI_ + B_ * D_) {
        attn_out = o + B_ * D_;
        mix_out  = o + B_ * D_ + B_ * TI_;
    }

    cudaFuncSetAttribute(k_scores_mma, cudaFuncAttributeMaxDynamicSharedMemorySize, SMEM_SC);

    k_prep<<<256, 256>>>(Wk);
    k_query<<<B_, 512>>>(outp, Wq, bq, bk);
    k_scores_mma<<<dim3(NCHUNK, M_TOTAL / 128), 256, SMEM_SC>>>(ctx, Wv);
    k_softmax<<<B_, 512>>>(attn_out);
    k_mix<<<dim3(TSPLIT, B_), 128>>>(ctx);
    k_out<<<B_, 512>>>(outp, Wo, bo, out_out, mix_out);
}

// round 8
// speedup vs baseline: 1.9086x; 1.1769x over previous
#include <cuda_runtime.h>
#include <cuda_bf16.h>
#include <math.h>
#include <stdint.h>

#define B_  32
#define TI_ 4096
#define D_  512
#define M_TOTAL (B_ * TI_)   /* 131072 */
#define NCHUNK 4             /* 512 / 128 n-chunks */
#define TSPLIT 16

// ---------------------------------------------------------------------------
// Device scratch (allocation-free; every element written before read each call)
// ---------------------------------------------------------------------------
__device__ float g_qk[B_ * D_];
__device__ float g_scores_part[NCHUNK * M_TOTAL];
__device__ float g_attn[M_TOTAL];
__device__ float g_mix_part[TSPLIT * B_ * D_];
__device__ uint32_t g_WkT[D_ * D_];   // Wk rounded to tf32 (raw b32 patterns)

// SW128 swizzle (Swizzle<3,4,3>) on tile-relative byte offsets
#define SWZ(off) ((off) ^ (((off) >> 3) & 0x70))

__device__ __forceinline__ uint32_t smem_u32(const void* p) {
    uint32_t a;
    asm("{ .reg .u64 t; cvta.to.shared.u64 t, %1; cvt.u32.u64 %0, t; }" : "=r"(a) : "l"(p));
    return a;
}
// cvt.rna.tf32.f32 writes a .b32 destination (raw tf32 bit pattern)
__device__ __forceinline__ uint32_t to_tf32(float x) {
    uint32_t r;
    asm("cvt.rna.tf32.f32 %0, %1;" : "=r"(r) : "f"(x));
    return r;
}
__device__ __forceinline__ void ldsm4(uint32_t* r, uint32_t addr) {
    asm volatile("ldmatrix.sync.aligned.m8n8.x4.shared.b16 {%0,%1,%2,%3}, [%4];"
                 : "=r"(r[0]), "=r"(r[1]), "=r"(r[2]), "=r"(r[3]) : "r"(addr));
}
__device__ __forceinline__ void mma_tf32(float* c, const uint32_t* a, uint32_t b0, uint32_t b1) {
    asm volatile("mma.sync.aligned.m16n8k8.row.col.f32.tf32.tf32.f32 "
                 "{%0,%1,%2,%3}, {%4,%5,%6,%7}, {%8,%9}, {%0,%1,%2,%3};"
                 : "+f"(c[0]), "+f"(c[1]), "+f"(c[2]), "+f"(c[3])
                 : "r"(a[0]), "r"(a[1]), "r"(a[2]), "r"(a[3]), "r"(b0), "r"(b1));
}
__device__ __forceinline__ void cp_async16(uint32_t dst, const void* src) {
    asm volatile("cp.async.cg.shared.global [%0], [%1], 16;" :: "r"(dst), "l"(src));
}
#define CP_COMMIT() asm volatile("cp.async.commit_group;" ::: "memory")
#define CP_WAIT0()  asm volatile("cp.async.wait_group 0;" ::: "memory")

__device__ __forceinline__ float fast_tanhf(float x) {
    // tanh(x) = 1 - 2/(exp(2x)+1); exact at saturation
    return 1.0f - 2.0f / (__expf(2.0f * x) + 1.0f);
}

// ---------------------------------------------------------------------------
// SMEM layout for k_scores_mma (66 KB): per stage A(128x32 tf32)=16KB,
// B(128x32 tf32)=16KB. Rows = 128B, SW128-swizzled.
// ---------------------------------------------------------------------------
#define OFF_A0  0
#define OFF_B0  16384
#define OFF_A1  32768
#define OFF_B1  49152
#define OFF_QK  65536          /* 128 floats */
#define OFF_WV  66048          /* 128 floats */
#define OFF_RED 66560          /* 2 x 128 floats */
#define SMEM_SC 67584

// ---------------------------------------------------------------------------
// k_prep: Wk fp32 -> tf32-rounded raw b32 (1 MB), layout [n][k]
// ---------------------------------------------------------------------------
__global__ void k_prep(const float* __restrict__ Wk) {
    int idx = blockIdx.x * 256 + threadIdx.x;       // 65536 threads, float4 each
    float4 v = ((const float4*)Wk)[idx];
    uint4 o;
    o.x = to_tf32(v.x); o.y = to_tf32(v.y); o.z = to_tf32(v.z); o.w = to_tf32(v.w);
    ((uint4*)g_WkT)[idx] = o;
}

// ---------------------------------------------------------------------------
// k_query: g_qk[b][d] = output[b] . Wq[d] + bq[d] + bk[d]
// ---------------------------------------------------------------------------
__global__ void k_query(const float* __restrict__ outp, const float* __restrict__ Wq,
                        const float* __restrict__ bq, const float* __restrict__ bk) {
    __shared__ float so[D_];
    int b = blockIdx.x, tid = threadIdx.x;          // 512 threads
    so[tid] = outp[b * D_ + tid];
    __syncthreads();
    int warp = tid >> 5, lane = tid & 31;
    for (int d = warp; d < D_; d += 16) {
        const float* w = Wq + (size_t)d * D_;
        float s = 0.f;
#pragma unroll 4
        for (int j = lane; j < D_; j += 32) s += so[j] * w[j];
#pragma unroll
        for (int o = 16; o > 0; o >>= 1) s += __shfl_down_sync(0xffffffffu, s, o);
        if (lane == 0) g_qk[b * D_ + d] = s + bq[d] + bk[d];
    }
}

// ---------------------------------------------------------------------------
// Stage-fill pieces. A (ctx): LDG early, tf32-cvt+STS late. B (WkT): cp.async.
// ---------------------------------------------------------------------------
__device__ __forceinline__ void ldA(const float* __restrict__ ctx,
                                    int m0, int kc, int tid, float4* Av) {
    const int col0 = kc * 32;
#pragma unroll
    for (int it = 0; it < 4; ++it) {
        int j = tid + it * 256;
        int row = j >> 3, seg = j & 7;
        Av[it] = *(const float4*)(ctx + (size_t)(m0 + row) * D_ + col0 + seg * 4);
    }
}

__device__ __forceinline__ void cvtStoreA(char* smA, int tid, const float4* Av) {
#pragma unroll
    for (int it = 0; it < 4; ++it) {
        int j = tid + it * 256;
        int row = j >> 3, seg = j & 7;
        float4 v = Av[it];
        uint4 o;
        o.x = to_tf32(v.x); o.y = to_tf32(v.y); o.z = to_tf32(v.z); o.w = to_tf32(v.w);
        *(uint4*)(smA + SWZ((uint32_t)(row * 128 + seg * 16))) = o;
    }
}

__device__ __forceinline__ void cpB(int n0, int kc, uint32_t smB, int tid) {
    const int col0 = kc * 32;
#pragma unroll
    for (int it = 0; it < 4; ++it) {
        int j = tid + it * 256;
        int row = j >> 3, seg = j & 7;
        const uint32_t* src = g_WkT + (size_t)(n0 + row) * D_ + col0 + seg * 4;
        cp_async16(smB + SWZ((uint32_t)(row * 128 + seg * 16)), src);
    }
}

// ---------------------------------------------------------------------------
// k_scores_mma (dominant): single-pass tf32 GEMM via mma.sync.m16n8k8
// + tanh/Wv epilogue. Grid (NCHUNK, 1024), 256 threads (8 warps, 32m x 64n).
// ---------------------------------------------------------------------------
__global__ void __launch_bounds__(256, 1)
k_scores_mma(const float* __restrict__ ctx, const float* __restrict__ Wv) {
    extern __shared__ char smem[];
    const int tid  = threadIdx.x;
    const int lane = tid & 31, wid = tid >> 5;
    const int wm = wid >> 1, wn = wid & 1;
    const int n0 = blockIdx.x * 128;
    const int m0 = blockIdx.y * 128;
    const int b  = m0 >> 12;

    float* sQk  = (float*)(smem + OFF_QK);
    float* sWv  = (float*)(smem + OFF_WV);
    float* sred = (float*)(smem + OFF_RED);
    if (tid < 128) { sQk[tid] = g_qk[b * D_ + n0 + tid]; sWv[tid] = Wv[n0 + tid]; }

    // per-lane ldmatrix address constants (tf32 = b16 pairs; same tile scheme)
    const int q = lane >> 3, r = lane & 7;
    const uint32_t rowA  = wm * 32 + ((q & 1) << 3) + r;   // tiles: +8 rows (q&1), +16B (q>>1)
    const uint32_t segA  = (q >> 1) << 4;
    const uint32_t xorA  = (rowA & 7) << 4;
    const uint32_t baseA = rowA << 7;
    const uint32_t rowB  = wn * 64 + ((q >> 1) << 3) + r;  // tiles: +16B (q&1), +8 rows (q>>1)
    const uint32_t segB  = (q & 1) << 4;
    const uint32_t xorB  = (rowB & 7) << 4;
    const uint32_t baseB = rowB << 7;

    const uint32_t sb = smem_u32(smem);
    const uint32_t sA[2]  = { sb + OFF_A0, sb + OFF_A1 };
    const uint32_t sBa[2] = { sb + OFF_B0, sb + OFF_B1 };
    char* const smA[2] = { smem + OFF_A0, smem + OFF_A1 };

    float acc[2][8][4];
#pragma unroll
    for (int mi = 0; mi < 2; ++mi)
#pragma unroll
        for (int nt = 0; nt < 8; ++nt)
#pragma unroll
            for (int c = 0; c < 4; ++c) acc[mi][nt][c] = 0.f;

    float4 Av[4];
    // Prologue: fill stage 0
    cpB(n0, 0, sBa[0], tid);
    CP_COMMIT();
    ldA(ctx, m0, 0, tid, Av);
    cvtStoreA(smA[0], tid, Av);
    CP_WAIT0();
    __syncthreads();

    for (int kc = 0; kc < 16; ++kc) {
        const int s = kc & 1;
        if (kc + 1 < 16) {
            cpB(n0, kc + 1, sBa[1 - s], tid);   // async fill of other B stage
            CP_COMMIT();
            ldA(ctx, m0, kc + 1, tid, Av);       // LDG in flight during MMAs
        }

#pragma unroll
        for (int ks = 0; ks < 4; ++ks) {         // 4 k8-steps per 32-col chunk
            uint32_t a[2][4];    // [mi][4]
            uint32_t bb[4][4];   // [np-pair][4]
#pragma unroll
            for (int mi = 0; mi < 2; ++mi)
                ldsm4(a[mi], sA[s] + baseA + mi * 2048 +
                      (((uint32_t)(ks * 32) + segA) ^ xorA));
#pragma unroll
            for (int p = 0; p < 4; ++p)
                ldsm4(bb[p], sBa[s] + baseB + p * 2048 +
                      (((uint32_t)(ks * 32) + segB) ^ xorB));
#pragma unroll
            for (int mi = 0; mi < 2; ++mi)
#pragma unroll
                for (int np = 0; np < 8; ++np) {
                    const uint32_t* bp = bb[np >> 1] + ((np & 1) ? 2 : 0);
                    mma_tf32(acc[mi][np], a[mi], bp[0], bp[1]);
                }
        }

        if (kc + 1 < 16) cvtStoreA(smA[1 - s], tid, Av);   // convert+STS after MMAs
        CP_WAIT0();
        __syncthreads();
    }

    // Epilogue: score_part[row] = sum_n Wv[n] * tanh(acc + qk[n]) over 128 cols
#pragma unroll
    for (int mi = 0; mi < 2; ++mi) {
#pragma unroll
        for (int part = 0; part < 2; ++part) {
            float s = 0.f;
#pragma unroll
            for (int nt = 0; nt < 8; ++nt) {
                int col = wn * 64 + nt * 8 + 2 * (lane & 3);
                s += sWv[col]     * fast_tanhf(acc[mi][nt][part * 2]     + sQk[col]);
                s += sWv[col + 1] * fast_tanhf(acc[mi][nt][part * 2 + 1] + sQk[col + 1]);
            }
            s += __shfl_xor_sync(0xffffffffu, s, 1);
            s += __shfl_xor_sync(0xffffffffu, s, 2);
            if ((lane & 3) == 0)
                sred[wn * 128 + wm * 32 + mi * 16 + part * 8 + (lane >> 2)] = s;
        }
    }
    __syncthreads();
    if (tid < 128)
        g_scores_part[blockIdx.x * M_TOTAL + m0 + tid] = sred[tid] + sred[128 + tid];
}

// ---------------------------------------------------------------------------
// k_softmax: sum n-chunk partials, softmax over TI per batch (512 threads)
// ---------------------------------------------------------------------------
__global__ void k_softmax(float* __restrict__ attn_out) {
    __shared__ float s[TI_];
    __shared__ float red[512];
    int b = blockIdx.x, tid = threadIdx.x;   // 512 threads

    for (int t = tid; t < TI_; t += 512) {
        float v = 0.f;
#pragma unroll
        for (int p = 0; p < NCHUNK; ++p) v += g_scores_part[p * M_TOTAL + b * TI_ + t];
        s[t] = v;
    }
    __syncthreads();

    float m = -1e30f;
    for (int t = tid; t < TI_; t += 512) m = fmaxf(m, s[t]);
    red[tid] = m; __syncthreads();
    for (int o = 256; o > 0; o >>= 1) {
        if (tid < o) red[tid] = fmaxf(red[tid], red[tid + o]);
        __syncthreads();
    }
    m = red[0]; __syncthreads();

    float sum = 0.f;
    for (int t = tid; t < TI_; t += 512) { float e = expf(s[t] - m); s[t] = e; sum += e; }
    red[tid] = sum; __syncthreads();
    for (int o = 256; o > 0; o >>= 1) {
        if (tid < o) red[tid] += red[tid + o];
        __syncthreads();
    }
    float inv = 1.f / red[0];

    for (int t = tid; t < TI_; t += 512) {
        float av = s[t] * inv;
        g_attn[b * TI_ + t] = av;
        if (attn_out) attn_out[b * TI_ + t] = av;
    }
}

// ---------------------------------------------------------------------------
// k_mix: mix partials over 256-token splits, float4 loads
// ---------------------------------------------------------------------------
__global__ void k_mix(const float* __restrict__ ctx) {
    __shared__ float sa[256];
    int b = blockIdx.y, t0 = blockIdx.x * 256, tid = threadIdx.x;  // 128 threads
    sa[tid]       = g_attn[b * TI_ + t0 + tid];
    sa[tid + 128] = g_attn[b * TI_ + t0 + tid + 128];
    __syncthreads();
    const float4* cp = (const float4*)(ctx + ((size_t)b * TI_ + t0) * D_);
    float4 acc = make_float4(0.f, 0.f, 0.f, 0.f);
#pragma unroll 8
    for (int t = 0; t < 256; ++t) {
        float av = sa[t];
        float4 v = cp[(size_t)t * 128 + tid];
        acc.x += av * v.x; acc.y += av * v.y; acc.z += av * v.z; acc.w += av * v.w;
    }
    ((float4*)&g_mix_part[(blockIdx.x * B_ + b) * D_])[tid] = acc;
}

// ---------------------------------------------------------------------------
// k_out: reduce mix partials, concat with output, Wo projection + tanh
// ---------------------------------------------------------------------------
__global__ void k_out(const float* __restrict__ outp, const float* __restrict__ Wo,
                      const float* __restrict__ bo, float* __restrict__ out_out,
                      float* __restrict__ mix_out) {
    __shared__ float comb[2 * D_];
    int b = blockIdx.x, tid = threadIdx.x;   // 512 threads
    float mv = 0.f;
#pragma unroll
    for (int sp = 0; sp < TSPLIT; ++sp) mv += g_mix_part[(sp * B_ + b) * D_ + tid];
    comb[tid] = mv;
    if (mix_out) mix_out[b * D_ + tid] = mv;
    comb[D_ + tid] = outp[b * D_ + tid];
    __syncthreads();

    int warp = tid >> 5, lane = tid & 31;
    for (int d = warp; d < D_; d += 16) {
        const float* w = Wo + (size_t)d * (2 * D_);
        float s = 0.f;
#pragma unroll 4
        for (int j = lane; j < 2 * D_; j += 32) s += comb[j] * w[j];
#pragma unroll
        for (int o = 16; o > 0; o >>= 1) s += __shfl_down_sync(0xffffffffu, s, o);
        if (lane == 0) out_out[b * D_ + d] = tanhf(s + bo[d]);
    }
}

// ---------------------------------------------------------------------------
extern "C" void kernel_launch(void* const* d_in, const int* in_sizes, int n_in,
                              void* d_out, int out_size) {
    (void)in_sizes; (void)n_in;
    const float* outp = (const float*)d_in[0];
    const float* ctx  = (const float*)d_in[1];
    const float* Wq   = (const float*)d_in[2];
    const float* bq   = (const float*)d_in[3];
    const float* Wk   = (const float*)d_in[4];
    const float* bk   = (const float*)d_in[5];
    const float* Wv   = (const float*)d_in[6];
    /* d_in[7] = bv: cancels in softmax */
    const float* Wo   = (const float*)d_in[8];
    const float* bo   = (const float*)d_in[9];

    float* o        = (float*)d_out;
    float* out_out  = o;
    float* attn_out = nullptr;
    float* mix_out  = nullptr;
    if (out_size >= B_ * D_ + B_ * TI_ + B_ * D_) {
        attn_out = o + B_ * D_;
        mix_out  = o + B_ * D_ + B_ * TI_;
    }

    cudaFuncSetAttribute(k_scores_mma, cudaFuncAttributeMaxDynamicSharedMemorySize, SMEM_SC);

    k_prep<<<256, 256>>>(Wk);
    k_query<<<B_, 512>>>(outp, Wq, bq, bk);
    k_scores_mma<<<dim3(NCHUNK, M_TOTAL / 128), 256, SMEM_SC>>>(ctx, Wv);
    k_softmax<<<B_, 512>>>(attn_out);
    k_mix<<<dim3(TSPLIT, B_), 128>>>(ctx);
    k_out<<<B_, 512>>>(outp, Wo, bo, out_out, mix_out);
}

// round 9
// speedup vs baseline: 2.1887x; 1.1467x over previous
#include <cuda_runtime.h>
#include <cuda_bf16.h>
#include <math.h>
#include <stdint.h>

#define B_  32
#define TI_ 4096
#define D_  512
#define M_TOTAL (B_ * TI_)   /* 131072 */
#define NCHUNK 4             /* 512 / 128 n-chunks */
#define TSPLIT 16

// ---------------------------------------------------------------------------
// Device scratch (allocation-free; every element written before read each call)
// ---------------------------------------------------------------------------
__device__ float g_qk[B_ * D_];
__device__ float g_scores_part[NCHUNK * M_TOTAL];
__device__ float g_attn[M_TOTAL];
__device__ float g_mix_part[TSPLIT * B_ * D_];
__device__ uint32_t g_WkT[D_ * D_];   // Wk rounded to tf32 (raw b32 patterns)

// SW128 swizzle (Swizzle<3,4,3>) on tile-relative byte offsets
#define SWZ(off) ((off) ^ (((off) >> 3) & 0x70))

__device__ __forceinline__ uint32_t smem_u32(const void* p) {
    uint32_t a;
    asm("{ .reg .u64 t; cvta.to.shared.u64 t, %1; cvt.u32.u64 %0, t; }" : "=r"(a) : "l"(p));
    return a;
}
// cvt.rna.tf32.f32 writes a .b32 destination (raw tf32 bit pattern)
__device__ __forceinline__ uint32_t to_tf32(float x) {
    uint32_t r;
    asm("cvt.rna.tf32.f32 %0, %1;" : "=r"(r) : "f"(x));
    return r;
}
__device__ __forceinline__ void ldsm4(uint32_t* r, uint32_t addr) {
    asm volatile("ldmatrix.sync.aligned.m8n8.x4.shared.b16 {%0,%1,%2,%3}, [%4];"
                 : "=r"(r[0]), "=r"(r[1]), "=r"(r[2]), "=r"(r[3]) : "r"(addr));
}
__device__ __forceinline__ void mma_tf32(float* c, const uint32_t* a, uint32_t b0, uint32_t b1) {
    asm volatile("mma.sync.aligned.m16n8k8.row.col.f32.tf32.tf32.f32 "
                 "{%0,%1,%2,%3}, {%4,%5,%6,%7}, {%8,%9}, {%0,%1,%2,%3};"
                 : "+f"(c[0]), "+f"(c[1]), "+f"(c[2]), "+f"(c[3])
                 : "r"(a[0]), "r"(a[1]), "r"(a[2]), "r"(a[3]), "r"(b0), "r"(b1));
}
__device__ __forceinline__ void cp_async16(uint32_t dst, const void* src) {
    asm volatile("cp.async.cg.shared.global [%0], [%1], 16;" :: "r"(dst), "l"(src));
}
#define CP_COMMIT() asm volatile("cp.async.commit_group;" ::: "memory")
#define CP_WAIT0()  asm volatile("cp.async.wait_group 0;" ::: "memory")

__device__ __forceinline__ float fast_tanhf(float x) {
    // tanh(x) = 1 - 2/(exp(2x)+1); exact at saturation
    return 1.0f - 2.0f / (__expf(2.0f * x) + 1.0f);
}

// ---------------------------------------------------------------------------
// SMEM layout for k_scores_mma (66 KB): per stage A(128x32 tf32)=16KB,
// B(128x32 tf32)=16KB. Rows = 128B, SW128-swizzled. 2 CTAs/SM fit (132KB).
// ---------------------------------------------------------------------------
#define OFF_A0  0
#define OFF_B0  16384
#define OFF_A1  32768
#define OFF_B1  49152
#define OFF_QK  65536          /* 128 floats */
#define OFF_WV  66048          /* 128 floats */
#define OFF_RED 66560          /* 2 x 128 floats */
#define SMEM_SC 67584

// ---------------------------------------------------------------------------
// k_prep: Wk fp32 -> tf32-rounded raw b32 (1 MB), layout [n][k]
// ---------------------------------------------------------------------------
__global__ void k_prep(const float* __restrict__ Wk) {
    int idx = blockIdx.x * 256 + threadIdx.x;       // 65536 threads, float4 each
    float4 v = ((const float4*)Wk)[idx];
    uint4 o;
    o.x = to_tf32(v.x); o.y = to_tf32(v.y); o.z = to_tf32(v.z); o.w = to_tf32(v.w);
    ((uint4*)g_WkT)[idx] = o;
}

// ---------------------------------------------------------------------------
// k_query: g_qk[b][d] = output[b] . Wq[d] + bq[d] + bk[d]
// ---------------------------------------------------------------------------
__global__ void k_query(const float* __restrict__ outp, const float* __restrict__ Wq,
                        const float* __restrict__ bq, const float* __restrict__ bk) {
    __shared__ float so[D_];
    int b = blockIdx.x, tid = threadIdx.x;          // 512 threads
    so[tid] = outp[b * D_ + tid];
    __syncthreads();
    int warp = tid >> 5, lane = tid & 31;
    for (int d = warp; d < D_; d += 16) {
        const float* w = Wq + (size_t)d * D_;
        float s = 0.f;
#pragma unroll 4
        for (int j = lane; j < D_; j += 32) s += so[j] * w[j];
#pragma unroll
        for (int o = 16; o > 0; o >>= 1) s += __shfl_down_sync(0xffffffffu, s, o);
        if (lane == 0) g_qk[b * D_ + d] = s + bq[d] + bk[d];
    }
}

// ---------------------------------------------------------------------------
// Stage-fill pieces. A (ctx): LDG early, tf32-cvt+STS late. B (WkT): cp.async.
// ---------------------------------------------------------------------------
__device__ __forceinline__ void ldA(const float* __restrict__ ctx,
                                    int m0, int kc, int tid, float4* Av) {
    const int col0 = kc * 32;
#pragma unroll
    for (int it = 0; it < 4; ++it) {
        int j = tid + it * 256;
        int row = j >> 3, seg = j & 7;
        Av[it] = *(const float4*)(ctx + (size_t)(m0 + row) * D_ + col0 + seg * 4);
    }
}

__device__ __forceinline__ void cvtStoreA(char* smA, int tid, const float4* Av) {
#pragma unroll
    for (int it = 0; it < 4; ++it) {
        int j = tid + it * 256;
        int row = j >> 3, seg = j & 7;
        float4 v = Av[it];
        uint4 o;
        o.x = to_tf32(v.x); o.y = to_tf32(v.y); o.z = to_tf32(v.z); o.w = to_tf32(v.w);
        *(uint4*)(smA + SWZ((uint32_t)(row * 128 + seg * 16))) = o;
    }
}

__device__ __forceinline__ void cpB(int n0, int kc, uint32_t smB, int tid) {
    const int col0 = kc * 32;
#pragma unroll
    for (int it = 0; it < 4; ++it) {
        int j = tid + it * 256;
        int row = j >> 3, seg = j & 7;
        const uint32_t* src = g_WkT + (size_t)(n0 + row) * D_ + col0 + seg * 4;
        cp_async16(smB + SWZ((uint32_t)(row * 128 + seg * 16)), src);
    }
}

// ---------------------------------------------------------------------------
// k_scores_mma (dominant): single-pass tf32 GEMM via mma.sync.m16n8k8
// + tanh/Wv epilogue. Grid (NCHUNK, 1024), 256 threads (8 warps, 32m x 64n).
// 2 CTAs/SM: co-resident CTA hides load/convert/sync/epilogue phases.
// ---------------------------------------------------------------------------
__global__ void __launch_bounds__(256, 2)
k_scores_mma(const float* __restrict__ ctx, const float* __restrict__ Wv) {
    extern __shared__ char smem[];
    const int tid  = threadIdx.x;
    const int lane = tid & 31, wid = tid >> 5;
    const int wm = wid >> 1, wn = wid & 1;
    const int n0 = blockIdx.x * 128;
    const int m0 = blockIdx.y * 128;
    const int b  = m0 >> 12;

    float* sQk  = (float*)(smem + OFF_QK);
    float* sWv  = (float*)(smem + OFF_WV);
    float* sred = (float*)(smem + OFF_RED);
    if (tid < 128) { sQk[tid] = g_qk[b * D_ + n0 + tid]; sWv[tid] = Wv[n0 + tid]; }

    // per-lane ldmatrix address constants (tf32 = b16 pairs; same tile scheme)
    const int q = lane >> 3, r = lane & 7;
    const uint32_t rowA  = wm * 32 + ((q & 1) << 3) + r;
    const uint32_t segA  = (q >> 1) << 4;
    const uint32_t xorA  = (rowA & 7) << 4;
    const uint32_t baseA = rowA << 7;
    const uint32_t rowB  = wn * 64 + ((q >> 1) << 3) + r;
    const uint32_t segB  = (q & 1) << 4;
    const uint32_t xorB  = (rowB & 7) << 4;
    const uint32_t baseB = rowB << 7;

    const uint32_t sb = smem_u32(smem);
    const uint32_t sA[2]  = { sb + OFF_A0, sb + OFF_A1 };
    const uint32_t sBa[2] = { sb + OFF_B0, sb + OFF_B1 };
    char* const smA[2] = { smem + OFF_A0, smem + OFF_A1 };

    float acc[2][8][4];
#pragma unroll
    for (int mi = 0; mi < 2; ++mi)
#pragma unroll
        for (int nt = 0; nt < 8; ++nt)
#pragma unroll
            for (int c = 0; c < 4; ++c) acc[mi][nt][c] = 0.f;

    float4 Av[4];
    // Prologue: fill stage 0
    cpB(n0, 0, sBa[0], tid);
    CP_COMMIT();
    ldA(ctx, m0, 0, tid, Av);
    cvtStoreA(smA[0], tid, Av);
    CP_WAIT0();
    __syncthreads();

    for (int kc = 0; kc < 16; ++kc) {
        const int s = kc & 1;
        if (kc + 1 < 16) {
            cpB(n0, kc + 1, sBa[1 - s], tid);   // async fill of other B stage
            CP_COMMIT();
            ldA(ctx, m0, kc + 1, tid, Av);       // LDG in flight during MMAs
        }

#pragma unroll
        for (int ks = 0; ks < 4; ++ks) {         // 4 k8-steps per 32-col chunk
            uint32_t a[2][4];    // [mi][4]
            uint32_t bb[4][4];   // [np-pair][4]
#pragma unroll
            for (int mi = 0; mi < 2; ++mi)
                ldsm4(a[mi], sA[s] + baseA + mi * 2048 +
                      (((uint32_t)(ks * 32) + segA) ^ xorA));
#pragma unroll
            for (int p = 0; p < 4; ++p)
                ldsm4(bb[p], sBa[s] + baseB + p * 2048 +
                      (((uint32_t)(ks * 32) + segB) ^ xorB));
#pragma unroll
            for (int mi = 0; mi < 2; ++mi)
#pragma unroll
                for (int np = 0; np < 8; ++np) {
                    const uint32_t* bp = bb[np >> 1] + ((np & 1) ? 2 : 0);
                    mma_tf32(acc[mi][np], a[mi], bp[0], bp[1]);
                }
        }

        if (kc + 1 < 16) cvtStoreA(smA[1 - s], tid, Av);   // convert+STS after MMAs
        CP_WAIT0();
        __syncthreads();
    }

    // Epilogue: score_part[row] = sum_n Wv[n] * tanh(acc + qk[n]) over 128 cols
#pragma unroll
    for (int mi = 0; mi < 2; ++mi) {
#pragma unroll
        for (int part = 0; part < 2; ++part) {
            float s = 0.f;
#pragma unroll
            for (int nt = 0; nt < 8; ++nt) {
                int col = wn * 64 + nt * 8 + 2 * (lane & 3);
                s += sWv[col]     * fast_tanhf(acc[mi][nt][part * 2]     + sQk[col]);
                s += sWv[col + 1] * fast_tanhf(acc[mi][nt][part * 2 + 1] + sQk[col + 1]);
            }
            s += __shfl_xor_sync(0xffffffffu, s, 1);
            s += __shfl_xor_sync(0xffffffffu, s, 2);
            if ((lane & 3) == 0)
                sred[wn * 128 + wm * 32 + mi * 16 + part * 8 + (lane >> 2)] = s;
        }
    }
    __syncthreads();
    if (tid < 128)
        g_scores_part[blockIdx.x * M_TOTAL + m0 + tid] = sred[tid] + sred[128 + tid];
}

// ---------------------------------------------------------------------------
// k_softmax: sum n-chunk partials, softmax over TI per batch (512 threads)
// ---------------------------------------------------------------------------
__global__ void k_softmax(float* __restrict__ attn_out) {
    __shared__ float s[TI_];
    __shared__ float red[512];
    int b = blockIdx.x, tid = threadIdx.x;   // 512 threads

    for (int t = tid; t < TI_; t += 512) {
        float v = 0.f;
#pragma unroll
        for (int p = 0; p < NCHUNK; ++p) v += g_scores_part[p * M_TOTAL + b * TI_ + t];
        s[t] = v;
    }
    __syncthreads();

    float m = -1e30f;
    for (int t = tid; t < TI_; t += 512) m = fmaxf(m, s[t]);
    red[tid] = m; __syncthreads();
    for (int o = 256; o > 0; o >>= 1) {
        if (tid < o) red[tid] = fmaxf(red[tid], red[tid + o]);
        __syncthreads();
    }
    m = red[0]; __syncthreads();

    float sum = 0.f;
    for (int t = tid; t < TI_; t += 512) { float e = expf(s[t] - m); s[t] = e; sum += e; }
    red[tid] = sum; __syncthreads();
    for (int o = 256; o > 0; o >>= 1) {
        if (tid < o) red[tid] += red[tid + o];
        __syncthreads();
    }
    float inv = 1.f / red[0];

    for (int t = tid; t < TI_; t += 512) {
        float av = s[t] * inv;
        g_attn[b * TI_ + t] = av;
        if (attn_out) attn_out[b * TI_ + t] = av;
    }
}

// ---------------------------------------------------------------------------
// k_mix: mix partials over 256-token splits, float4 loads
// ---------------------------------------------------------------------------
__global__ void k_mix(const float* __restrict__ ctx) {
    __shared__ float sa[256];
    int b = blockIdx.y, t0 = blockIdx.x * 256, tid = threadIdx.x;  // 128 threads
    sa[tid]       = g_attn[b * TI_ + t0 + tid];
    sa[tid + 128] = g_attn[b * TI_ + t0 + tid + 128];
    __syncthreads();
    const float4* cp = (const float4*)(ctx + ((size_t)b * TI_ + t0) * D_);
    float4 acc = make_float4(0.f, 0.f, 0.f, 0.f);
#pragma unroll 8
    for (int t = 0; t < 256; ++t) {
        float av = sa[t];
        float4 v = cp[(size_t)t * 128 + tid];
        acc.x += av * v.x; acc.y += av * v.y; acc.z += av * v.z; acc.w += av * v.w;
    }
    ((float4*)&g_mix_part[(blockIdx.x * B_ + b) * D_])[tid] = acc;
}

// ---------------------------------------------------------------------------
// k_out: reduce mix partials, concat with output, Wo projection + tanh
// ---------------------------------------------------------------------------
__global__ void k_out(const float* __restrict__ outp, const float* __restrict__ Wo,
                      const float* __restrict__ bo, float* __restrict__ out_out,
                      float* __restrict__ mix_out) {
    __shared__ float comb[2 * D_];
    int b = blockIdx.x, tid = threadIdx.x;   // 512 threads
    float mv = 0.f;
#pragma unroll
    for (int sp = 0; sp < TSPLIT; ++sp) mv += g_mix_part[(sp * B_ + b) * D_ + tid];
    comb[tid] = mv;
    if (mix_out) mix_out[b * D_ + tid] = mv;
    comb[D_ + tid] = outp[b * D_ + tid];
    __syncthreads();

    int warp = tid >> 5, lane = tid & 31;
    for (int d = warp; d < D_; d += 16) {
        const float* w = Wo + (size_t)d * (2 * D_);
        float s = 0.f;
#pragma unroll 4
        for (int j = lane; j < 2 * D_; j += 32) s += comb[j] * w[j];
#pragma unroll
        for (int o = 16; o > 0; o >>= 1) s += __shfl_down_sync(0xffffffffu, s, o);
        if (lane == 0) out_out[b * D_ + d] = tanhf(s + bo[d]);
    }
}

// ---------------------------------------------------------------------------
extern "C" void kernel_launch(void* const* d_in, const int* in_sizes, int n_in,
                              void* d_out, int out_size) {
    (void)in_sizes; (void)n_in;
    const float* outp = (const float*)d_in[0];
    const float* ctx  = (const float*)d_in[1];
    const float* Wq   = (const float*)d_in[2];
    const float* bq   = (const float*)d_in[3];
    const float* Wk   = (const float*)d_in[4];
    const float* bk   = (const float*)d_in[5];
    const float* Wv   = (const float*)d_in[6];
    /* d_in[7] = bv: cancels in softmax */
    const float* Wo   = (const float*)d_in[8];
    const float* bo   = (const float*)d_in[9];

    float* o        = (float*)d_out;
    float* out_out  = o;
    float* attn_out = nullptr;
    float* mix_out  = nullptr;
    if (out_size >= B_ * D_ + B_ * TI_ + B_ * D_) {
        attn_out = o + B_ * D_;
        mix_out  = o + B_ * D_ + B_ * TI_;
    }

    cudaFuncSetAttribute(k_scores_mma, cudaFuncAttributeMaxDynamicSharedMemorySize, SMEM_SC);

    k_prep<<<256, 256>>>(Wk);
    k_query<<<B_, 512>>>(outp, Wq, bq, bk);
    k_scores_mma<<<dim3(NCHUNK, M_TOTAL / 128), 256, SMEM_SC>>>(ctx, Wv);
    k_softmax<<<B_, 512>>>(attn_out);
    k_mix<<<dim3(TSPLIT, B_), 128>>>(ctx);
    k_out<<<B_, 512>>>(outp, Wo, bo, out_out, mix_out);
}

// round 11
// speedup vs baseline: 2.3854x; 1.0898x over previous
#include <cuda_runtime.h>
#include <cuda_bf16.h>
#include <math.h>
#include <stdint.h>

#define B_  32
#define TI_ 4096
#define D_  512
#define M_TOTAL (B_ * TI_)   /* 131072 */
#define NCHUNK 4             /* 512 / 128 n-chunks */
#define TSPLIT 16

// ---------------------------------------------------------------------------
// Device scratch (allocation-free; every element written before read each call)
// ---------------------------------------------------------------------------
__device__ float g_qk[B_ * D_];
__device__ float g_scores_part[NCHUNK * M_TOTAL];
__device__ float g_attn[M_TOTAL];
__device__ float g_mix_part[TSPLIT * B_ * D_];
__device__ uint32_t g_WkT[D_ * D_];                      // Wk tf32 (raw b32)
__device__ uint32_t g_ctxT[(size_t)M_TOTAL * D_];        // ctx tf32 (raw b32, 256 MB)

// SW128 swizzle (Swizzle<3,4,3>) on tile-relative byte offsets
#define SWZ(off) ((off) ^ (((off) >> 3) & 0x70))

__device__ __forceinline__ uint32_t smem_u32(const void* p) {
    uint32_t a;
    asm("{ .reg .u64 t; cvta.to.shared.u64 t, %1; cvt.u32.u64 %0, t; }" : "=r"(a) : "l"(p));
    return a;
}
// cvt.rna.tf32.f32 writes a .b32 destination (raw tf32 bit pattern)
__device__ __forceinline__ uint32_t to_tf32(float x) {
    uint32_t r;
    asm("cvt.rna.tf32.f32 %0, %1;" : "=r"(r) : "f"(x));
    return r;
}
__device__ __forceinline__ void ldsm4(uint32_t* r, uint32_t addr) {
    asm volatile("ldmatrix.sync.aligned.m8n8.x4.shared.b16 {%0,%1,%2,%3}, [%4];"
                 : "=r"(r[0]), "=r"(r[1]), "=r"(r[2]), "=r"(r[3]) : "r"(addr));
}
__device__ __forceinline__ void mma_tf32(float* c, const uint32_t* a, uint32_t b0, uint32_t b1) {
    asm volatile("mma.sync.aligned.m16n8k8.row.col.f32.tf32.tf32.f32 "
                 "{%0,%1,%2,%3}, {%4,%5,%6,%7}, {%8,%9}, {%0,%1,%2,%3};"
                 : "+f"(c[0]), "+f"(c[1]), "+f"(c[2]), "+f"(c[3])
                 : "r"(a[0]), "r"(a[1]), "r"(a[2]), "r"(a[3]), "r"(b0), "r"(b1));
}
__device__ __forceinline__ void cp_async16(uint32_t dst, const void* src) {
    asm volatile("cp.async.cg.shared.global [%0], [%1], 16;" :: "r"(dst), "l"(src));
}
#define CP_COMMIT() asm volatile("cp.async.commit_group;" ::: "memory")
#define CP_WAIT0()  asm volatile("cp.async.wait_group 0;" ::: "memory")
#define CP_WAIT1()  asm volatile("cp.async.wait_group 1;" ::: "memory")

__device__ __forceinline__ float fast_tanhf(float x) {
    // tanh(x) = 1 - 2/(exp(2x)+1); exact at saturation
    return 1.0f - 2.0f / (__expf(2.0f * x) + 1.0f);
}

// ---------------------------------------------------------------------------
// SMEM layout for k_scores_mma: 3 stages x (A 16KB + B 16KB) = 96KB + tail.
// Rows = 128B, SW128-swizzled. 2 CTAs/SM (196KB < 228KB).
// ---------------------------------------------------------------------------
#define STG_SZ  32768
#define OFF_QK  98304          /* 128 floats */
#define OFF_WV  98816          /* 128 floats */
#define OFF_RED 99328          /* 2 x 128 floats */
#define SMEM_SC 100352

// ---------------------------------------------------------------------------
// k_prep: Wk fp32 -> tf32 raw b32 (1 MB)
// ---------------------------------------------------------------------------
__global__ void k_prep(const float* __restrict__ Wk) {
    int idx = blockIdx.x * 256 + threadIdx.x;       // 65536 float4 jobs
    float4 v = ((const float4*)Wk)[idx];
    uint4 o;
    o.x = to_tf32(v.x); o.y = to_tf32(v.y); o.z = to_tf32(v.z); o.w = to_tf32(v.w);
    ((uint4*)g_WkT)[idx] = o;
}

// ---------------------------------------------------------------------------
// k_prep_ctx: ctx fp32 -> tf32 raw b32 (256 MB); pure streaming pass
// ---------------------------------------------------------------------------
__global__ void k_prep_ctx(const float* __restrict__ ctx) {
    size_t idx = (size_t)blockIdx.x * 256 + threadIdx.x;   // 16M float4 jobs
    float4 v = ((const float4*)ctx)[idx];
    uint4 o;
    o.x = to_tf32(v.x); o.y = to_tf32(v.y); o.z = to_tf32(v.z); o.w = to_tf32(v.w);
    ((uint4*)g_ctxT)[idx] = o;
}

// ---------------------------------------------------------------------------
// k_query: g_qk[b][d] = output[b] . Wq[d] + bq[d] + bk[d]
// ---------------------------------------------------------------------------
__global__ void k_query(const float* __restrict__ outp, const float* __restrict__ Wq,
                        const float* __restrict__ bq, const float* __restrict__ bk) {
    __shared__ float so[D_];
    int b = blockIdx.x, tid = threadIdx.x;          // 512 threads
    so[tid] = outp[b * D_ + tid];
    __syncthreads();
    int warp = tid >> 5, lane = tid & 31;
    for (int d = warp; d < D_; d += 16) {
        const float* w = Wq + (size_t)d * D_;
        float s = 0.f;
#pragma unroll 4
        for (int j = lane; j < D_; j += 32) s += so[j] * w[j];
#pragma unroll
        for (int o = 16; o > 0; o >>= 1) s += __shfl_down_sync(0xffffffffu, s, o);
        if (lane == 0) g_qk[b * D_ + d] = s + bq[d] + bk[d];
    }
}

// ---------------------------------------------------------------------------
// cp.async stage fills (4 x 16B per thread each; no registers, no cvt)
// ---------------------------------------------------------------------------
__device__ __forceinline__ void cpA(int m0, int kc, uint32_t smA, int tid) {
    const int col0 = kc * 32;
#pragma unroll
    for (int it = 0; it < 4; ++it) {
        int j = tid + it * 256;
        int row = j >> 3, seg = j & 7;
        const uint32_t* src = g_ctxT + (size_t)(m0 + row) * D_ + col0 + seg * 4;
        cp_async16(smA + SWZ((uint32_t)(row * 128 + seg * 16)), src);
    }
}
__device__ __forceinline__ void cpB(int n0, int kc, uint32_t smB, int tid) {
    const int col0 = kc * 32;
#pragma unroll
    for (int it = 0; it < 4; ++it) {
        int j = tid + it * 256;
        int row = j >> 3, seg = j & 7;
        const uint32_t* src = g_WkT + (size_t)(n0 + row) * D_ + col0 + seg * 4;
        cp_async16(smB + SWZ((uint32_t)(row * 128 + seg * 16)), src);
    }
}

// ---------------------------------------------------------------------------
// k_scores_mma (dominant): tf32 mma.sync GEMM, 3-stage cp.async ring,
// tanh/Wv epilogue. Grid (NCHUNK, 1024), 256 threads (8 warps, 32m x 64n).
// ---------------------------------------------------------------------------
__global__ void __launch_bounds__(256, 2)
k_scores_mma(const float* __restrict__ Wv) {
    extern __shared__ char smem[];
    const int tid  = threadIdx.x;
    const int lane = tid & 31, wid = tid >> 5;
    const int wm = wid >> 1, wn = wid & 1;
    const int n0 = blockIdx.x * 128;
    const int m0 = blockIdx.y * 128;
    const int b  = m0 >> 12;

    float* sQk  = (float*)(smem + OFF_QK);
    float* sWv  = (float*)(smem + OFF_WV);
    float* sred = (float*)(smem + OFF_RED);
    if (tid < 128) { sQk[tid] = g_qk[b * D_ + n0 + tid]; sWv[tid] = Wv[n0 + tid]; }

    // per-lane ldmatrix address constants (tf32 = b16 pairs; same tile scheme)
    const int q = lane >> 3, r = lane & 7;
    const uint32_t rowA  = wm * 32 + ((q & 1) << 3) + r;
    const uint32_t segA  = (q >> 1) << 4;
    const uint32_t xorA  = (rowA & 7) << 4;
    const uint32_t baseA = rowA << 7;
    const uint32_t rowB  = wn * 64 + ((q >> 1) << 3) + r;
    const uint32_t segB  = (q & 1) << 4;
    const uint32_t xorB  = (rowB & 7) << 4;
    const uint32_t baseB = rowB << 7;

    const uint32_t sb = smem_u32(smem);

    float acc[2][8][4];
#pragma unroll
    for (int mi = 0; mi < 2; ++mi)
#pragma unroll
        for (int nt = 0; nt < 8; ++nt)
#pragma unroll
            for (int c = 0; c < 4; ++c) acc[mi][nt][c] = 0.f;

    // Prologue: stages 0 and 1 in flight
    cpA(m0, 0, sb + 0 * STG_SZ, tid); cpB(n0, 0, sb + 0 * STG_SZ + 16384, tid); CP_COMMIT();
    cpA(m0, 1, sb + 1 * STG_SZ, tid); cpB(n0, 1, sb + 1 * STG_SZ + 16384, tid); CP_COMMIT();

    int stg = 0;
    for (int kc = 0; kc < 16; ++kc) {
        if (kc < 14) CP_WAIT1(); else CP_WAIT0();   // stage kc resident
        __syncthreads();                            // all warps done with stage kc-1's buffer

        if (kc + 2 < 16) {                          // refill buffer (kc+2)%3 (held kc-1)
            int nstg = stg + 2; if (nstg >= 3) nstg -= 3;
            uint32_t base = sb + nstg * STG_SZ;
            cpA(m0, kc + 2, base, tid);
            cpB(n0, kc + 2, base + 16384, tid);
            CP_COMMIT();
        }

        const uint32_t sAs = sb + stg * STG_SZ;
        const uint32_t sBs = sAs + 16384;
#pragma unroll
        for (int ks = 0; ks < 4; ++ks) {            // 4 k8-steps per 32-col chunk
            uint32_t a[2][4];
            uint32_t bb[4][4];
#pragma unroll
            for (int mi = 0; mi < 2; ++mi)
                ldsm4(a[mi], sAs + baseA + mi * 2048 +
                      (((uint32_t)(ks * 32) + segA) ^ xorA));
#pragma unroll
            for (int p = 0; p < 4; ++p)
                ldsm4(bb[p], sBs + baseB + p * 2048 +
                      (((uint32_t)(ks * 32) + segB) ^ xorB));
#pragma unroll
            for (int mi = 0; mi < 2; ++mi)
#pragma unroll
                for (int np = 0; np < 8; ++np) {
                    const uint32_t* bp = bb[np >> 1] + ((np & 1) ? 2 : 0);
                    mma_tf32(acc[mi][np], a[mi], bp[0], bp[1]);
                }
        }
        if (++stg == 3) stg = 0;
    }

    // Epilogue: score_part[row] = sum_n Wv[n] * tanh(acc + qk[n]) over 128 cols
#pragma unroll
    for (int mi = 0; mi < 2; ++mi) {
#pragma unroll
        for (int part = 0; part < 2; ++part) {
            float s = 0.f;
#pragma unroll
            for (int nt = 0; nt < 8; ++nt) {
                int col = wn * 64 + nt * 8 + 2 * (lane & 3);
                s += sWv[col]     * fast_tanhf(acc[mi][nt][part * 2]     + sQk[col]);
                s += sWv[col + 1] * fast_tanhf(acc[mi][nt][part * 2 + 1] + sQk[col + 1]);
            }
            s += __shfl_xor_sync(0xffffffffu, s, 1);
            s += __shfl_xor_sync(0xffffffffu, s, 2);
            if ((lane & 3) == 0)
                sred[wn * 128 + wm * 32 + mi * 16 + part * 8 + (lane >> 2)] = s;
        }
    }
    __syncthreads();
    if (tid < 128)
        g_scores_part[blockIdx.x * M_TOTAL + m0 + tid] = sred[tid] + sred[128 + tid];
}

// ---------------------------------------------------------------------------
// k_softmax: sum n-chunk partials, softmax over TI per batch (512 threads)
// ---------------------------------------------------------------------------
__global__ void k_softmax(float* __restrict__ attn_out) {
    __shared__ float s[TI_];
    __shared__ float red[512];
    int b = blockIdx.x, tid = threadIdx.x;   // 512 threads

    for (int t = tid; t < TI_; t += 512) {
        float v = 0.f;
#pragma unroll
        for (int p = 0; p < NCHUNK; ++p) v += g_scores_part[p * M_TOTAL + b * TI_ + t];
        s[t] = v;
    }
    __syncthreads();

    float m = -1e30f;
    for (int t = tid; t < TI_; t += 512) m = fmaxf(m, s[t]);
    red[tid] = m; __syncthreads();
    for (int o = 256; o > 0; o >>= 1) {
        if (tid < o) red[tid] = fmaxf(red[tid], red[tid + o]);
        __syncthreads();
    }
    m = red[0]; __syncthreads();

    float sum = 0.f;
    for (int t = tid; t < TI_; t += 512) { float e = expf(s[t] - m); s[t] = e; sum += e; }
    red[tid] = sum; __syncthreads();
    for (int o = 256; o > 0; o >>= 1) {
        if (tid < o) red[tid] += red[tid + o];
        __syncthreads();
    }
    float inv = 1.f / red[0];

    for (int t = tid; t < TI_; t += 512) {
        float av = s[t] * inv;
        g_attn[b * TI_ + t] = av;
        if (attn_out) attn_out[b * TI_ + t] = av;
    }
}

// ---------------------------------------------------------------------------
// k_mix: mix partials over 256-token splits, float4 loads (full-precision ctx)
// ---------------------------------------------------------------------------
__global__ void k_mix(const float* __restrict__ ctx) {
    __shared__ float sa[256];
    int b = blockIdx.y, t0 = blockIdx.x * 256, tid = threadIdx.x;  // 128 threads
    sa[tid]       = g_attn[b * TI_ + t0 + tid];
    sa[tid + 128] = g_attn[b * TI_ + t0 + tid + 128];
    __syncthreads();
    const float4* cp = (const float4*)(ctx + ((size_t)b * TI_ + t0) * D_);
    float4 acc = make_float4(0.f, 0.f, 0.f, 0.f);
#pragma unroll 8
    for (int t = 0; t < 256; ++t) {
        float av = sa[t];
        float4 v = cp[(size_t)t * 128 + tid];
        acc.x += av * v.x; acc.y += av * v.y; acc.z += av * v.z; acc.w += av * v.w;
    }
    ((float4*)&g_mix_part[(blockIdx.x * B_ + b) * D_])[tid] = acc;
}

// ---------------------------------------------------------------------------
// k_out: reduce mix partials, concat with output, Wo projection + tanh
// ---------------------------------------------------------------------------
__global__ void k_out(const float* __restrict__ outp, const float* __restrict__ Wo,
                      const float* __restrict__ bo, float* __restrict__ out_out,
                      float* __restrict__ mix_out) {
    __shared__ float comb[2 * D_];
    int b = blockIdx.x, tid = threadIdx.x;   // 512 threads
    float mv = 0.f;
#pragma unroll
    for (int sp = 0; sp < TSPLIT; ++sp) mv += g_mix_part[(sp * B_ + b) * D_ + tid];
    comb[tid] = mv;
    if (mix_out) mix_out[b * D_ + tid] = mv;
    comb[D_ + tid] = outp[b * D_ + tid];
    __syncthreads();

    int warp = tid >> 5, lane = tid & 31;
    for (int d = warp; d < D_; d += 16) {
        const float* w = Wo + (size_t)d * (2 * D_);
        float s = 0.f;
#pragma unroll 4
        for (int j = lane; j < 2 * D_; j += 32) s += comb[j] * w[j];
#pragma unroll
        for (int o = 16; o > 0; o >>= 1) s += __shfl_down_sync(0xffffffffu, s, o);
        if (lane == 0) out_out[b * D_ + d] = tanhf(s + bo[d]);
    }
}

// ---------------------------------------------------------------------------
extern "C" void kernel_launch(void* const* d_in, const int* in_sizes, int n_in,
                              void* d_out, int out_size) {
    (void)in_sizes; (void)n_in;
    const float* outp = (const float*)d_in[0];
    const float* ctx  = (const float*)d_in[1];
    const float* Wq   = (const float*)d_in[2];
    const float* bq   = (const float*)d_in[3];
    const float* Wk   = (const float*)d_in[4];
    const float* bk   = (const float*)d_in[5];
    const float* Wv   = (const float*)d_in[6];
    /* d_in[7] = bv: cancels in softmax */
    const float* Wo   = (const float*)d_in[8];
    const float* bo   = (const float*)d_in[9];

    float* o        = (float*)d_out;
    float* out_out  = o;
    float* attn_out = nullptr;
    float* mix_out  = nullptr;
    if (out_size >= B_ * D_ + B_ * TI_ + B_ * D_) {
        attn_out = o + B_ * D_;
        mix_out  = o + B_ * D_ + B_ * TI_;
    }

    cudaFuncSetAttribute(k_scores_mma, cudaFuncAttributeMaxDynamicSharedMemorySize, SMEM_SC);

    k_prep<<<256, 256>>>(Wk);
    k_prep_ctx<<<65536, 256>>>(ctx);
    k_query<<<B_, 512>>>(outp, Wq, bq, bk);
    k_scores_mma<<<dim3(NCHUNK, M_TOTAL / 128), 256, SMEM_SC>>>(Wv);
    k_softmax<<<B_, 512>>>(attn_out);
    k_mix<<<dim3(TSPLIT, B_), 128>>>(ctx);
    k_out<<<B_, 512>>>(outp, Wo, bo, out_out, mix_out);
}

// round 13
// speedup vs baseline: 2.6863x; 1.1262x over previous
#include <cuda_runtime.h>
#include <cuda_bf16.h>
#include <math.h>
#include <stdint.h>

#define B_  32
#define TI_ 4096
#define D_  512
#define M_TOTAL (B_ * TI_)   /* 131072 */
#define NCHUNK 4             /* 512 / 128 n-chunks */
#define TSPLIT 16

// ---------------------------------------------------------------------------
// Device scratch (allocation-free; every element written before read each call)
// ---------------------------------------------------------------------------
__device__ float g_qk[B_ * D_];
__device__ float g_scores_part[NCHUNK * M_TOTAL];
__device__ float g_attn[M_TOTAL];
__device__ float g_mix_part[TSPLIT * B_ * D_];
__device__ uint32_t g_WkT[D_ * D_];   // Wk tf32-rounded (raw b32)

// SW128 swizzle (Swizzle<3,4,3>) on tile-relative byte offsets
#define SWZ(off) ((off) ^ (((off) >> 3) & 0x70))

__device__ __forceinline__ uint32_t smem_u32(const void* p) {
    uint32_t a;
    asm("{ .reg .u64 t; cvta.to.shared.u64 t, %1; cvt.u32.u64 %0, t; }" : "=r"(a) : "l"(p));
    return a;
}
// cvt.rna.tf32.f32 writes a .b32 destination (raw tf32 bit pattern)
__device__ __forceinline__ uint32_t to_tf32(float x) {
    uint32_t r;
    asm("cvt.rna.tf32.f32 %0, %1;" : "=r"(r) : "f"(x));
    return r;
}
__device__ __forceinline__ void ldsm4(uint32_t* r, uint32_t addr) {
    asm volatile("ldmatrix.sync.aligned.m8n8.x4.shared.b16 {%0,%1,%2,%3}, [%4];"
                 : "=r"(r[0]), "=r"(r[1]), "=r"(r[2]), "=r"(r[3]) : "r"(addr));
}
__device__ __forceinline__ void mma_tf32(float* c, const uint32_t* a, uint32_t b0, uint32_t b1) {
    asm volatile("mma.sync.aligned.m16n8k8.row.col.f32.tf32.tf32.f32 "
                 "{%0,%1,%2,%3}, {%4,%5,%6,%7}, {%8,%9}, {%0,%1,%2,%3};"
                 : "+f"(c[0]), "+f"(c[1]), "+f"(c[2]), "+f"(c[3])
                 : "r"(a[0]), "r"(a[1]), "r"(a[2]), "r"(a[3]), "r"(b0), "r"(b1));
}
__device__ __forceinline__ void cp_async16(uint32_t dst, const void* src) {
    asm volatile("cp.async.cg.shared.global [%0], [%1], 16;" :: "r"(dst), "l"(src));
}
#define CP_COMMIT() asm volatile("cp.async.commit_group;" ::: "memory")
#define CP_WAIT0()  asm volatile("cp.async.wait_group 0;" ::: "memory")
#define CP_WAIT1()  asm volatile("cp.async.wait_group 1;" ::: "memory")

__device__ __forceinline__ float fast_tanhf(float x) {
    // tanh(x) = 1 - 2/(exp(2x)+1); exact at saturation
    return 1.0f - 2.0f / (__expf(2.0f * x) + 1.0f);
}

// ---------------------------------------------------------------------------
// SMEM layout for k_scores_mma: 3 stages x (A 16KB + B 16KB) = 96KB + tail.
// Rows = 128B, SW128-swizzled. 2 CTAs/SM (196KB < 228KB).
// ---------------------------------------------------------------------------
#define STG_SZ  32768
#define OFF_QK  98304          /* 128 floats */
#define OFF_WV  98816          /* 128 floats */
#define OFF_RED 99328          /* 2 x 128 floats */
#define SMEM_SC 100352

// ---------------------------------------------------------------------------
// k_prep: Wk fp32 -> tf32-rounded raw b32 (1 MB). B-side stays RN-rounded;
// A-side (ctx) is fed as raw fp32 and truncated by the tf32 datapath.
// ---------------------------------------------------------------------------
__global__ void k_prep(const float* __restrict__ Wk) {
    int idx = blockIdx.x * 256 + threadIdx.x;       // 65536 float4 jobs
    float4 v = ((const float4*)Wk)[idx];
    uint4 o;
    o.x = to_tf32(v.x); o.y = to_tf32(v.y); o.z = to_tf32(v.z); o.w = to_tf32(v.w);
    ((uint4*)g_WkT)[idx] = o;
}

// ---------------------------------------------------------------------------
// k_query: g_qk[b][d] = output[b] . Wq[d] + bq[d] + bk[d]
// ---------------------------------------------------------------------------
__global__ void k_query(const float* __restrict__ outp, const float* __restrict__ Wq,
                        const float* __restrict__ bq, const float* __restrict__ bk) {
    __shared__ float so[D_];
    int b = blockIdx.x, tid = threadIdx.x;          // 512 threads
    so[tid] = outp[b * D_ + tid];
    __syncthreads();
    int warp = tid >> 5, lane = tid & 31;
    for (int d = warp; d < D_; d += 16) {
        const float* w = Wq + (size_t)d * D_;
        float s = 0.f;
#pragma unroll 4
        for (int j = lane; j < D_; j += 32) s += so[j] * w[j];
#pragma unroll
        for (int o = 16; o > 0; o >>= 1) s += __shfl_down_sync(0xffffffffu, s, o);
        if (lane == 0) g_qk[b * D_ + d] = s + bq[d] + bk[d];
    }
}

// ---------------------------------------------------------------------------
// cp.async stage fills (4 x 16B per thread each; no registers, no cvt)
// A comes straight from the fp32 ctx input (tf32 HW truncates mantissa).
// ---------------------------------------------------------------------------
__device__ __forceinline__ void cpA(const float* __restrict__ ctx,
                                    int m0, int kc, uint32_t smA, int tid) {
    const int col0 = kc * 32;
#pragma unroll
    for (int it = 0; it < 4; ++it) {
        int j = tid + it * 256;
        int row = j >> 3, seg = j & 7;
        const float* src = ctx + (size_t)(m0 + row) * D_ + col0 + seg * 4;
        cp_async16(smA + SWZ((uint32_t)(row * 128 + seg * 16)), src);
    }
}
__device__ __forceinline__ void cpB(int n0, int kc, uint32_t smB, int tid) {
    const int col0 = kc * 32;
#pragma unroll
    for (int it = 0; it < 4; ++it) {
        int j = tid + it * 256;
        int row = j >> 3, seg = j & 7;
        const uint32_t* src = g_WkT + (size_t)(n0 + row) * D_ + col0 + seg * 4;
        cp_async16(smB + SWZ((uint32_t)(row * 128 + seg * 16)), src);
    }
}

// ---------------------------------------------------------------------------
// k_scores_mma (dominant): tf32 mma.sync GEMM, 3-stage cp.async ring,
// tanh/Wv epilogue. Grid (NCHUNK, 1024), 256 threads (8 warps, 32m x 64n).
// ---------------------------------------------------------------------------
__global__ void __launch_bounds__(256, 2)
k_scores_mma(const float* __restrict__ ctx, const float* __restrict__ Wv) {
    extern __shared__ char smem[];
    const int tid  = threadIdx.x;
    const int lane = tid & 31, wid = tid >> 5;
    const int wm = wid >> 1, wn = wid & 1;
    const int n0 = blockIdx.x * 128;
    const int m0 = blockIdx.y * 128;
    const int b  = m0 >> 12;

    float* sQk  = (float*)(smem + OFF_QK);
    float* sWv  = (float*)(smem + OFF_WV);
    float* sred = (float*)(smem + OFF_RED);
    if (tid < 128) { sQk[tid] = g_qk[b * D_ + n0 + tid]; sWv[tid] = Wv[n0 + tid]; }

    // per-lane ldmatrix address constants (tf32 = b16 pairs; same tile scheme)
    const int q = lane >> 3, r = lane & 7;
    const uint32_t rowA  = wm * 32 + ((q & 1) << 3) + r;
    const uint32_t segA  = (q >> 1) << 4;
    const uint32_t xorA  = (rowA & 7) << 4;
    const uint32_t baseA = rowA << 7;
    const uint32_t rowB  = wn * 64 + ((q >> 1) << 3) + r;
    const uint32_t segB  = (q & 1) << 4;
    const uint32_t xorB  = (rowB & 7) << 4;
    const uint32_t baseB = rowB << 7;

    const uint32_t sb = smem_u32(smem);

    float acc[2][8][4];
#pragma unroll
    for (int mi = 0; mi < 2; ++mi)
#pragma unroll
        for (int nt = 0; nt < 8; ++nt)
#pragma unroll
            for (int c = 0; c < 4; ++c) acc[mi][nt][c] = 0.f;

    // Prologue: stages 0 and 1 in flight
    cpA(ctx, m0, 0, sb + 0 * STG_SZ, tid); cpB(n0, 0, sb + 0 * STG_SZ + 16384, tid); CP_COMMIT();
    cpA(ctx, m0, 1, sb + 1 * STG_SZ, tid); cpB(n0, 1, sb + 1 * STG_SZ + 16384, tid); CP_COMMIT();

    int stg = 0;
    for (int kc = 0; kc < 16; ++kc) {
        if (kc < 14) CP_WAIT1(); else CP_WAIT0();   // stage kc resident
        __syncthreads();                            // all warps done with stage kc-1's buffer

        if (kc + 2 < 16) {                          // refill buffer (kc+2)%3 (held kc-1)
            int nstg = stg + 2; if (nstg >= 3) nstg -= 3;
            uint32_t base = sb + nstg * STG_SZ;
            cpA(ctx, m0, kc + 2, base, tid);
            cpB(n0, kc + 2, base + 16384, tid);
            CP_COMMIT();
        }

        const uint32_t sAs = sb + stg * STG_SZ;
        const uint32_t sBs = sAs + 16384;
#pragma unroll
        for (int ks = 0; ks < 4; ++ks) {            // 4 k8-steps per 32-col chunk
            uint32_t a[2][4];
            uint32_t bb[4][4];
#pragma unroll
            for (int mi = 0; mi < 2; ++mi)
                ldsm4(a[mi], sAs + baseA + mi * 2048 +
                      (((uint32_t)(ks * 32) + segA) ^ xorA));
#pragma unroll
            for (int p = 0; p < 4; ++p)
                ldsm4(bb[p], sBs + baseB + p * 2048 +
                      (((uint32_t)(ks * 32) + segB) ^ xorB));
#pragma unroll
            for (int mi = 0; mi < 2; ++mi)
#pragma unroll
                for (int np = 0; np < 8; ++np) {
                    const uint32_t* bp = bb[np >> 1] + ((np & 1) ? 2 : 0);
                    mma_tf32(acc[mi][np], a[mi], bp[0], bp[1]);
                }
        }
        if (++stg == 3) stg = 0;
    }

    // Epilogue: score_part[row] = sum_n Wv[n] * tanh(acc + qk[n]) over 128 cols
#pragma unroll
    for (int mi = 0; mi < 2; ++mi) {
#pragma unroll
        for (int part = 0; part < 2; ++part) {
            float s = 0.f;
#pragma unroll
            for (int nt = 0; nt < 8; ++nt) {
                int col = wn * 64 + nt * 8 + 2 * (lane & 3);
                s += sWv[col]     * fast_tanhf(acc[mi][nt][part * 2]     + sQk[col]);
                s += sWv[col + 1] * fast_tanhf(acc[mi][nt][part * 2 + 1] + sQk[col + 1]);
            }
            s += __shfl_xor_sync(0xffffffffu, s, 1);
            s += __shfl_xor_sync(0xffffffffu, s, 2);
            if ((lane & 3) == 0)
                sred[wn * 128 + wm * 32 + mi * 16 + part * 8 + (lane >> 2)] = s;
        }
    }
    __syncthreads();
    if (tid < 128)
        g_scores_part[blockIdx.x * M_TOTAL + m0 + tid] = sred[tid] + sred[128 + tid];
}

// ---------------------------------------------------------------------------
// k_softmax: sum n-chunk partials, softmax over TI per batch (512 threads)
// ---------------------------------------------------------------------------
__global__ void k_softmax(float* __restrict__ attn_out) {
    __shared__ float s[TI_];
    __shared__ float red[512];
    int b = blockIdx.x, tid = threadIdx.x;   // 512 threads

    for (int t = tid; t < TI_; t += 512) {
        float v = 0.f;
#pragma unroll
        for (int p = 0; p < NCHUNK; ++p) v += g_scores_part[p * M_TOTAL + b * TI_ + t];
        s[t] = v;
    }
    __syncthreads();

    float m = -1e30f;
    for (int t = tid; t < TI_; t += 512) m = fmaxf(m, s[t]);
    red[tid] = m; __syncthreads();
    for (int o = 256; o > 0; o >>= 1) {
        if (tid < o) red[tid] = fmaxf(red[tid], red[tid + o]);
        __syncthreads();
    }
    m = red[0]; __syncthreads();

    float sum = 0.f;
    for (int t = tid; t < TI_; t += 512) { float e = expf(s[t] - m); s[t] = e; sum += e; }
    red[tid] = sum; __syncthreads();
    for (int o = 256; o > 0; o >>= 1) {
        if (tid < o) red[tid] += red[tid + o];
        __syncthreads();
    }
    float inv = 1.f / red[0];

    for (int t = tid; t < TI_; t += 512) {
        float av = s[t] * inv;
        g_attn[b * TI_ + t] = av;
        if (attn_out) attn_out[b * TI_ + t] = av;
    }
}

// ---------------------------------------------------------------------------
// k_mix: mix partials over 256-token splits, float4 loads (full-precision ctx)
// ---------------------------------------------------------------------------
__global__ void k_mix(const float* __restrict__ ctx) {
    __shared__ float sa[256];
    int b = blockIdx.y, t0 = blockIdx.x * 256, tid = threadIdx.x;  // 128 threads
    sa[tid]       = g_attn[b * TI_ + t0 + tid];
    sa[tid + 128] = g_attn[b * TI_ + t0 + tid + 128];
    __syncthreads();
    const float4* cp = (const float4*)(ctx + ((size_t)b * TI_ + t0) * D_);
    float4 acc = make_float4(0.f, 0.f, 0.f, 0.f);
#pragma unroll 8
    for (int t = 0; t < 256; ++t) {
        float av = sa[t];
        float4 v = cp[(size_t)t * 128 + tid];
        acc.x += av * v.x; acc.y += av * v.y; acc.z += av * v.z; acc.w += av * v.w;
    }
    ((float4*)&g_mix_part[(blockIdx.x * B_ + b) * D_])[tid] = acc;
}

// ---------------------------------------------------------------------------
// k_out: reduce mix partials, concat with output, Wo projection + tanh
// ---------------------------------------------------------------------------
__global__ void k_out(const float* __restrict__ outp, const float* __restrict__ Wo,
                      const float* __restrict__ bo, float* __restrict__ out_out,
                      float* __restrict__ mix_out) {
    __shared__ float comb[2 * D_];
    int b = blockIdx.x, tid = threadIdx.x;   // 512 threads
    float mv = 0.f;
#pragma unroll
    for (int sp = 0; sp < TSPLIT; ++sp) mv += g_mix_part[(sp * B_ + b) * D_ + tid];
    comb[tid] = mv;
    if (mix_out) mix_out[b * D_ + tid] = mv;
    comb[D_ + tid] = outp[b * D_ + tid];
    __syncthreads();

    int warp = tid >> 5, lane = tid & 31;
    for (int d = warp; d < D_; d += 16) {
        const float* w = Wo + (size_t)d * (2 * D_);
        float s = 0.f;
#pragma unroll 4
        for (int j = lane; j < 2 * D_; j += 32) s += comb[j] * w[j];
#pragma unroll
        for (int o = 16; o > 0; o >>= 1) s += __shfl_down_sync(0xffffffffu, s, o);
        if (lane == 0) out_out[b * D_ + d] = tanhf(s + bo[d]);
    }
}

// ---------------------------------------------------------------------------
extern "C" void kernel_launch(void* const* d_in, const int* in_sizes, int n_in,
                              void* d_out, int out_size) {
    (void)in_sizes; (void)n_in;
    const float* outp = (const float*)d_in[0];
    const float* ctx  = (const float*)d_in[1];
    const float* Wq   = (const float*)d_in[2];
    const float* bq   = (const float*)d_in[3];
    const float* Wk   = (const float*)d_in[4];
    const float* bk   = (const float*)d_in[5];
    const float* Wv   = (const float*)d_in[6];
    /* d_in[7] = bv: cancels in softmax */
    const float* Wo   = (const float*)d_in[8];
    const float* bo   = (const float*)d_in[9];

    float* o        = (float*)d_out;
    float* out_out  = o;
    float* attn_out = nullptr;
    float* mix_out  = nullptr;
    if (out_size >= B_ * D_ + B_ * TI_ + B_ * D_) {
        attn_out = o + B_ * D_;
        mix_out  = o + B_ * D_ + B_ * TI_;
    }

    cudaFuncSetAttribute(k_scores_mma, cudaFuncAttributeMaxDynamicSharedMemorySize, SMEM_SC);

    k_prep<<<256, 256>>>(Wk);
    k_query<<<B_, 512>>>(outp, Wq, bq, bk);
    k_scores_mma<<<dim3(NCHUNK, M_TOTAL / 128), 256, SMEM_SC>>>(ctx, Wv);
    k_softmax<<<B_, 512>>>(attn_out);
    k_mix<<<dim3(TSPLIT, B_), 128>>>(ctx);
    k_out<<<B_, 512>>>(outp, Wo, bo, out_out, mix_out);
}